// round 1
// baseline (speedup 1.0000x reference)
#include <cuda_runtime.h>
#include <math.h>

// Problem constants
constexpr int B_ = 4, L_ = 2048, D_ = 1024, H_ = 16, HD_ = 64;
constexpr int M_ = B_ * L_;          // 8192 rows (tokens)
constexpr int WINDOW_ = 128;
constexpr int QT = 64;               // queries per attention block
constexpr int KROWS = QT + WINDOW_ - 1;   // 191 key rows per block
constexpr int KPAD = 192;

// Scratch (device globals — allocation-free per harness rules)
__device__ float g_Q[(size_t)B_ * H_ * L_ * HD_];   // [B,H,L,hd]
__device__ float g_K[(size_t)B_ * H_ * L_ * HD_];
__device__ float g_V[(size_t)B_ * H_ * L_ * HD_];
__device__ float g_S[(size_t)M_ * D_];              // attention out, [B,L,D]

// ---------------------------------------------------------------------------
// GEMM: C[r,c] = sum_k A[r,k] * W[c,k]   (i.e. A @ W^T), A:[M_,D_], W:[D_,D_]
// 128x128 tile, K-step 8, 256 threads, 8x8 accumulators per thread.
// OUT_HEADS=1 scatters into [B,H,L,hd] layout; 0 writes row-major [M_,D_].
// ---------------------------------------------------------------------------
template <int OUT_HEADS>
__global__ void __launch_bounds__(256) gemm128(const float* __restrict__ A,
                                               const float* __restrict__ W,
                                               float* __restrict__ out) {
    __shared__ float As[8][132];
    __shared__ float Bs[8][132];

    const int t = threadIdx.x;
    const int tx = t & 15, ty = t >> 4;
    const int r0 = blockIdx.y << 7;
    const int c0 = blockIdx.x << 7;
    const int lr = t >> 1;            // 0..127 tile row
    const int lk = (t & 1) << 2;      // 0 or 4

    const float* Ag = A + (size_t)(r0 + lr) * D_ + lk;
    const float* Wg = W + (size_t)(c0 + lr) * D_ + lk;

    float acc[8][8];
#pragma unroll
    for (int i = 0; i < 8; i++)
#pragma unroll
        for (int j = 0; j < 8; j++) acc[i][j] = 0.f;

    for (int kt = 0; kt < D_; kt += 8) {
        float4 av = *(const float4*)(Ag + kt);
        float4 wv = *(const float4*)(Wg + kt);
        As[lk + 0][lr] = av.x; As[lk + 1][lr] = av.y;
        As[lk + 2][lr] = av.z; As[lk + 3][lr] = av.w;
        Bs[lk + 0][lr] = wv.x; Bs[lk + 1][lr] = wv.y;
        Bs[lk + 2][lr] = wv.z; Bs[lk + 3][lr] = wv.w;
        __syncthreads();

#pragma unroll
        for (int kk = 0; kk < 8; kk++) {
            float a[8], b[8];
#pragma unroll
            for (int i = 0; i < 8; i++) a[i] = As[kk][ty + (i << 4)];
#pragma unroll
            for (int j = 0; j < 8; j++) b[j] = Bs[kk][tx + (j << 4)];
#pragma unroll
            for (int i = 0; i < 8; i++)
#pragma unroll
                for (int j = 0; j < 8; j++)
                    acc[i][j] = fmaf(a[i], b[j], acc[i][j]);
        }
        __syncthreads();
    }

#pragma unroll
    for (int i = 0; i < 8; i++) {
        const int r = r0 + ty + (i << 4);
#pragma unroll
        for (int j = 0; j < 8; j++) {
            const int c = c0 + tx + (j << 4);
            if (OUT_HEADS) {
                const int bb = r >> 11;           // r / L_
                const int l  = r & (L_ - 1);
                const int h  = c >> 6;            // c / HD_
                const int d  = c & (HD_ - 1);
                out[(((size_t)bb * H_ + h) * L_ + l) * HD_ + d] = acc[i][j];
            } else {
                out[(size_t)r * D_ + c] = acc[i][j];
            }
        }
    }
}

// ---------------------------------------------------------------------------
// RoPE in-place over [B,H,L,hd]. One thread per (row, pair j<32).
// ---------------------------------------------------------------------------
__global__ void rope_kernel(float* __restrict__ x) {
    const int i = blockIdx.x * blockDim.x + threadIdx.x;
    if (i >= B_ * H_ * L_ * 32) return;
    const int j   = i & 31;
    const int row = i >> 5;                 // (b*H + h)*L + l
    const int l   = row & (L_ - 1);

    // inv_freq = 10000^(-j/32) = exp(-j * ln(10000)/32)
    const float invf = expf(-(float)j * 0.28782313662425575f);
    const float ang  = (float)l * invf;
    float s, c;
    sincosf(ang, &s, &c);

    const size_t base = (size_t)row * HD_;
    const float x0 = x[base + j];
    const float x1 = x[base + j + 32];
    x[base + j]      = x0 * c - x1 * s;
    x[base + j + 32] = x1 * c + x0 * s;
}

// ---------------------------------------------------------------------------
// Sliding-window causal attention.
// Block = (q-tile of 64, one (b,h)). 8 warps, each warp owns 8 queries.
// K/V for rows [q0-127, q0+63] staged in dynamic SMEM (2 * 192*64*4 = 96 KB).
// ---------------------------------------------------------------------------
__global__ void __launch_bounds__(256) attn_kernel() {
    extern __shared__ float sh[];
    float* Ks = sh;
    float* Vs = sh + KPAD * HD_;

    const int bh  = blockIdx.y;               // (b*H + h)
    const int q0  = blockIdx.x * QT;
    const int ks0 = q0 - (WINDOW_ - 1);       // may be negative

    const float* Kg = g_K + (size_t)bh * L_ * HD_;
    const float* Vg = g_V + (size_t)bh * L_ * HD_;

    for (int idx = threadIdx.x; idx < KROWS * (HD_ / 4); idx += 256) {
        const int row = idx >> 4;
        const int c4  = (idx & 15) << 2;
        const int kk  = ks0 + row;
        if (kk >= 0) {
            *(float4*)(Ks + row * HD_ + c4) = *(const float4*)(Kg + (size_t)kk * HD_ + c4);
            *(float4*)(Vs + row * HD_ + c4) = *(const float4*)(Vg + (size_t)kk * HD_ + c4);
        }
    }
    __syncthreads();

    const int warp = threadIdx.x >> 5;
    const int lane = threadIdx.x & 31;
    const int bb = bh >> 4;            // b
    const int h  = bh & (H_ - 1);

    for (int qi = 0; qi < QT / 8; qi++) {
        const int q = q0 + warp * 8 + qi;
        const float* Qg = g_Q + ((size_t)bh * L_ + q) * HD_;
        const float qr0 = Qg[lane];
        const float qr1 = Qg[lane + 32];

        const int kstart = max(0, q - (WINDOW_ - 1));
        const int cnt = q - kstart + 1;          // <= 128 valid keys

        float sc[4] = {-1e30f, -1e30f, -1e30f, -1e30f};
#pragma unroll
        for (int blk = 0; blk < 4; blk++) {
            const int lo = blk * 32;
            const int hi = min(cnt, lo + 32);
            for (int ki = lo; ki < hi; ki++) {
                const int j = kstart + ki - ks0;
                float p = qr0 * Ks[j * HD_ + lane] + qr1 * Ks[j * HD_ + lane + 32];
                p += __shfl_xor_sync(0xffffffffu, p, 16);
                p += __shfl_xor_sync(0xffffffffu, p, 8);
                p += __shfl_xor_sync(0xffffffffu, p, 4);
                p += __shfl_xor_sync(0xffffffffu, p, 2);
                p += __shfl_xor_sync(0xffffffffu, p, 1);
                if (lane == (ki - lo)) sc[blk] = p * 0.125f;   // * hd^-0.5
            }
        }

        float m = fmaxf(fmaxf(sc[0], sc[1]), fmaxf(sc[2], sc[3]));
#pragma unroll
        for (int o = 16; o > 0; o >>= 1)
            m = fmaxf(m, __shfl_xor_sync(0xffffffffu, m, o));

        float e[4], sum = 0.f;
#pragma unroll
        for (int blk = 0; blk < 4; blk++) {
            e[blk] = expf(sc[blk] - m);   // -1e30 entries -> 0
            sum += e[blk];
        }
#pragma unroll
        for (int o = 16; o > 0; o >>= 1)
            sum += __shfl_xor_sync(0xffffffffu, sum, o);
        const float inv = 1.f / sum;

        float acc0 = 0.f, acc1 = 0.f;
#pragma unroll
        for (int blk = 0; blk < 4; blk++) {
            const int lo = blk * 32;
            const int hi = min(cnt, lo + 32);
            const float eb = e[blk];
            for (int ki = lo; ki < hi; ki++) {
                const float p = __shfl_sync(0xffffffffu, eb, ki - lo);
                const int j = kstart + ki - ks0;
                acc0 = fmaf(p, Vs[j * HD_ + lane], acc0);
                acc1 = fmaf(p, Vs[j * HD_ + lane + 32], acc1);
            }
        }

        float* O = g_S + ((size_t)bb * L_ + q) * D_ + h * HD_;
        O[lane]      = acc0 * inv;
        O[lane + 32] = acc1 * inv;
    }
}

// ---------------------------------------------------------------------------
// Launch: QKV proj (head layout) -> RoPE(Q,K) -> windowed attn -> O proj
// ---------------------------------------------------------------------------
extern "C" void kernel_launch(void* const* d_in, const int* in_sizes, int n_in,
                              void* d_out, int out_size) {
    const float* X  = (const float*)d_in[0];
    const float* Wq = (const float*)d_in[1];
    const float* Wk = (const float*)d_in[2];
    const float* Wv = (const float*)d_in[3];
    const float* Wo = (const float*)d_in[4];
    float* out = (float*)d_out;

    float *Q, *K, *V, *S;
    cudaGetSymbolAddress((void**)&Q, g_Q);
    cudaGetSymbolAddress((void**)&K, g_K);
    cudaGetSymbolAddress((void**)&V, g_V);
    cudaGetSymbolAddress((void**)&S, g_S);

    const dim3 gg(D_ / 128, M_ / 128);   // (8, 64)
    gemm128<1><<<gg, 256>>>(X, Wq, Q);
    gemm128<1><<<gg, 256>>>(X, Wk, K);
    gemm128<1><<<gg, 256>>>(X, Wv, V);

    const int rt = B_ * H_ * L_ * 32;
    rope_kernel<<<(rt + 255) / 256, 256>>>(Q);
    rope_kernel<<<(rt + 255) / 256, 256>>>(K);

    const int smem = 2 * KPAD * HD_ * (int)sizeof(float);   // 98304
    cudaFuncSetAttribute(attn_kernel, cudaFuncAttributeMaxDynamicSharedMemorySize, smem);
    attn_kernel<<<dim3(L_ / QT, B_ * H_), 256, smem>>>();

    gemm128<0><<<gg, 256>>>(S, Wo, out);
}

// round 3
// speedup vs baseline: 1.6686x; 1.6686x over previous
#include <cuda_runtime.h>
#include <cuda_bf16.h>
#include <math.h>
#include <stdint.h>

// Problem constants
constexpr int B_ = 4, L_ = 2048, D_ = 1024, H_ = 16, HD_ = 64;
constexpr int M_ = B_ * L_;
constexpr int WINDOW_ = 128;
constexpr int QT = 64;
constexpr int KROWS = QT + WINDOW_ - 1;
constexpr int KPAD = 192;

// GEMM tiling (mma.sync path — works on plain sm_100 target)
constexpr int TM = 128, TN = 128, KS = 32;
constexpr int NK = D_ / KS;                 // 32 k-steps
constexpr int ROWB = 80;                    // padded row: 32 bf16 = 64B -> 80B
constexpr int TILE_B = 128 * ROWB;          // 10240 B per operand tile
constexpr int STAGE_B = 4 * TILE_B;         // Ahi, Alo, Whi, Wlo
constexpr int GSMEM = 2 * STAGE_B;          // 81920 B

// Scratch (device globals — allocation-free per harness rules)
__device__ float g_Q[(size_t)B_ * H_ * L_ * HD_];
__device__ float g_K[(size_t)B_ * H_ * L_ * HD_];
__device__ float g_V[(size_t)B_ * H_ * L_ * HD_];
__device__ float g_S[(size_t)M_ * D_];
__device__ __nv_bfloat16 g_Xhi[(size_t)M_ * D_];
__device__ __nv_bfloat16 g_Xlo[(size_t)M_ * D_];
__device__ __nv_bfloat16 g_Shi[(size_t)M_ * D_];
__device__ __nv_bfloat16 g_Slo[(size_t)M_ * D_];
__device__ __nv_bfloat16 g_Whi[4ull * D_ * D_];
__device__ __nv_bfloat16 g_Wlo[4ull * D_ * D_];

__device__ __forceinline__ uint32_t smem_u32(const void* p) {
    uint32_t a;
    asm("{ .reg .u64 t; cvta.to.shared.u64 t, %1; cvt.u32.u64 %0, t; }" : "=r"(a) : "l"(p));
    return a;
}

#define LDSM4(r, addr) \
    asm volatile("ldmatrix.sync.aligned.m8n8.x4.shared.b16 {%0,%1,%2,%3}, [%4];" \
                 : "=r"((r)[0]), "=r"((r)[1]), "=r"((r)[2]), "=r"((r)[3]) : "r"(addr))

#define MMA16816(d, a, b0, b1) \
    asm volatile("mma.sync.aligned.m16n8k16.row.col.f32.bf16.bf16.f32 " \
                 "{%0,%1,%2,%3}, {%4,%5,%6,%7}, {%8,%9}, {%0,%1,%2,%3};" \
                 : "+f"((d)[0]), "+f"((d)[1]), "+f"((d)[2]), "+f"((d)[3]) \
                 : "r"((a)[0]), "r"((a)[1]), "r"((a)[2]), "r"((a)[3]), "r"(b0), "r"(b1))

#define CP_WAIT(n) asm volatile("cp.async.wait_group %0;" :: "n"(n) : "memory")

__device__ __forceinline__ void cp16(uint32_t sa, const void* g) {
    asm volatile("cp.async.cg.shared.global [%0], [%1], 16;" :: "r"(sa), "l"(g));
}

// Stage one K-chunk: 4 operand tiles (Ahi, Alo, Whi, Wlo), each 128 rows x 64B.
__device__ __forceinline__ void cp_stage(char* st, const __nv_bfloat16* t0,
                                         const __nv_bfloat16* t1, const __nv_bfloat16* t2,
                                         const __nv_bfloat16* t3, int ko, int tid) {
    const __nv_bfloat16* gp[4] = {t0, t1, t2, t3};
    const uint32_t sb = smem_u32(st);
#pragma unroll
    for (int t = 0; t < 4; t++) {
#pragma unroll
        for (int rep = 0; rep < 2; rep++) {
            const int c = rep * 256 + tid;
            const int row = c >> 2, ch = c & 3;
            cp16(sb + t * TILE_B + row * ROWB + ch * 16,
                 gp[t] + (size_t)row * D_ + ko + ch * 8);
        }
    }
    asm volatile("cp.async.commit_group;" ::: "memory");
}

// ---------------------------------------------------------------------------
// bf16 hi/lo split GEMM via mma.sync: C[8192,1024] = A @ W^T
// CTA 128x128, K-step 32, 8 warps (2x4), warp tile 64x32, double-buffered.
// ---------------------------------------------------------------------------
template <int OUT_HEADS>
__global__ void __launch_bounds__(256) gemm_mma(const __nv_bfloat16* __restrict__ Ahi,
                                                const __nv_bfloat16* __restrict__ Alo,
                                                const __nv_bfloat16* __restrict__ Whi,
                                                const __nv_bfloat16* __restrict__ Wlo,
                                                float* __restrict__ out) {
    extern __shared__ char sm[];
    const int tid = threadIdx.x;
    const int lane = tid & 31, wid = tid >> 5;
    const int mw = wid & 1, nw = wid >> 1;        // 2 m-warps x 4 n-warps
    const int r0 = blockIdx.y * TM, n0 = blockIdx.x * TN;

    const __nv_bfloat16* Ahi_t = Ahi + (size_t)r0 * D_;
    const __nv_bfloat16* Alo_t = Alo + (size_t)r0 * D_;
    const __nv_bfloat16* Whi_t = Whi + (size_t)n0 * D_;
    const __nv_bfloat16* Wlo_t = Wlo + (size_t)n0 * D_;

    float acc[4][4][4];
#pragma unroll
    for (int i = 0; i < 4; i++)
#pragma unroll
        for (int j = 0; j < 4; j++)
#pragma unroll
            for (int k = 0; k < 4; k++) acc[i][j][k] = 0.f;

    cp_stage(sm, Ahi_t, Alo_t, Whi_t, Wlo_t, 0, tid);

    for (int kc = 0; kc < NK; kc++) {
        const int s = kc & 1;
        if (kc + 1 < NK) {
            cp_stage(sm + (s ^ 1) * STAGE_B, Ahi_t, Alo_t, Whi_t, Wlo_t, (kc + 1) * KS, tid);
            CP_WAIT(1);
        } else {
            CP_WAIT(0);
        }
        __syncthreads();

        const uint32_t sb = smem_u32(sm + s * STAGE_B);
        const uint32_t lrow15 = (lane & 15);
        const uint32_t lhalf  = (lane >> 4) * 16;
#pragma unroll
        for (int kt = 0; kt < 2; kt++) {
            uint32_t bh[2][4], bl[2][4];
#pragma unroll
            for (int np = 0; np < 2; np++) {
                const uint32_t ba = sb + 2 * TILE_B +
                    (nw * 32 + np * 16 + lrow15) * ROWB + kt * 32 + lhalf;
                LDSM4(bh[np], ba);
                LDSM4(bl[np], ba + TILE_B);
            }
#pragma unroll
            for (int mt = 0; mt < 4; mt++) {
                uint32_t ah[4], al[4];
                const uint32_t aa = sb +
                    (mw * 64 + mt * 16 + lrow15) * ROWB + kt * 32 + lhalf;
                LDSM4(ah, aa);
                LDSM4(al, aa + TILE_B);
#pragma unroll
                for (int nt = 0; nt < 4; nt++) {
                    const uint32_t b0h = bh[nt >> 1][nt & 1], b1h = bh[nt >> 1][(nt & 1) + 2];
                    const uint32_t b0l = bl[nt >> 1][nt & 1], b1l = bl[nt >> 1][(nt & 1) + 2];
                    MMA16816(acc[mt][nt], ah, b0h, b1h);
                    MMA16816(acc[mt][nt], ah, b0l, b1l);
                    MMA16816(acc[mt][nt], al, b0h, b1h);
                }
            }
        }
        __syncthreads();
    }

    // Epilogue
#pragma unroll
    for (int mt = 0; mt < 4; mt++) {
#pragma unroll
        for (int nt = 0; nt < 4; nt++) {
            const int row = r0 + mw * 64 + mt * 16 + (lane >> 2);
            const int col = n0 + nw * 32 + nt * 8 + 2 * (lane & 3);
            float* d0;
            float* d1;
            if (OUT_HEADS) {
                const int h = col >> 6, dd = col & 63;
                const int bb0 = row >> 11, l0 = row & (L_ - 1);
                d0 = out + (((size_t)bb0 * H_ + h) * L_ + l0) * HD_ + dd;
                const int r8 = row + 8;
                const int bb1 = r8 >> 11, l1 = r8 & (L_ - 1);
                d1 = out + (((size_t)bb1 * H_ + h) * L_ + l1) * HD_ + dd;
            } else {
                d0 = out + (size_t)row * D_ + col;
                d1 = out + (size_t)(row + 8) * D_ + col;
            }
            *(float2*)d0 = make_float2(acc[mt][nt][0], acc[mt][nt][1]);
            *(float2*)d1 = make_float2(acc[mt][nt][2], acc[mt][nt][3]);
        }
    }
}

// ---------------------------------------------------------------------------
// fp32 -> (bf16 hi, bf16 lo) split
// ---------------------------------------------------------------------------
__global__ void split_kernel(const float4* __restrict__ x,
                             __nv_bfloat162* __restrict__ hi,
                             __nv_bfloat162* __restrict__ lo, int n4) {
    const int i = blockIdx.x * blockDim.x + threadIdx.x;
    if (i >= n4) return;
    const float4 v = x[i];
    const __nv_bfloat16 h0 = __float2bfloat16(v.x), h1 = __float2bfloat16(v.y);
    const __nv_bfloat16 h2 = __float2bfloat16(v.z), h3 = __float2bfloat16(v.w);
    const __nv_bfloat16 l0 = __float2bfloat16(v.x - __bfloat162float(h0));
    const __nv_bfloat16 l1 = __float2bfloat16(v.y - __bfloat162float(h1));
    const __nv_bfloat16 l2 = __float2bfloat16(v.z - __bfloat162float(h2));
    const __nv_bfloat16 l3 = __float2bfloat16(v.w - __bfloat162float(h3));
    hi[2 * i]     = __halves2bfloat162(h0, h1);
    hi[2 * i + 1] = __halves2bfloat162(h2, h3);
    lo[2 * i]     = __halves2bfloat162(l0, l1);
    lo[2 * i + 1] = __halves2bfloat162(l2, l3);
}

// ---------------------------------------------------------------------------
// RoPE in-place over [B,H,L,hd]
// ---------------------------------------------------------------------------
__global__ void rope_kernel(float* __restrict__ x) {
    const int i = blockIdx.x * blockDim.x + threadIdx.x;
    if (i >= B_ * H_ * L_ * 32) return;
    const int j = i & 31;
    const int row = i >> 5;
    const int l = row & (L_ - 1);
    const float invf = expf(-(float)j * 0.28782313662425575f);
    float s, c;
    sincosf((float)l * invf, &s, &c);
    const size_t base = (size_t)row * HD_;
    const float x0 = x[base + j];
    const float x1 = x[base + j + 32];
    x[base + j]      = x0 * c - x1 * s;
    x[base + j + 32] = x1 * c + x0 * s;
}

// ---------------------------------------------------------------------------
// Sliding-window causal attention (R0 passing version)
// ---------------------------------------------------------------------------
__global__ void __launch_bounds__(256) attn_kernel() {
    extern __shared__ float sh[];
    float* Ks = sh;
    float* Vs = sh + KPAD * HD_;

    const int bh = blockIdx.y;
    const int q0 = blockIdx.x * QT;
    const int ks0 = q0 - (WINDOW_ - 1);

    const float* Kg = g_K + (size_t)bh * L_ * HD_;
    const float* Vg = g_V + (size_t)bh * L_ * HD_;

    for (int idx = threadIdx.x; idx < KROWS * (HD_ / 4); idx += 256) {
        const int row = idx >> 4;
        const int c4 = (idx & 15) << 2;
        const int kk = ks0 + row;
        if (kk >= 0) {
            *(float4*)(Ks + row * HD_ + c4) = *(const float4*)(Kg + (size_t)kk * HD_ + c4);
            *(float4*)(Vs + row * HD_ + c4) = *(const float4*)(Vg + (size_t)kk * HD_ + c4);
        }
    }
    __syncthreads();

    const int warp = threadIdx.x >> 5;
    const int lane = threadIdx.x & 31;
    const int bb = bh >> 4;
    const int h = bh & (H_ - 1);

    for (int qi = 0; qi < QT / 8; qi++) {
        const int q = q0 + warp * 8 + qi;
        const float* Qg = g_Q + ((size_t)bh * L_ + q) * HD_;
        const float qr0 = Qg[lane];
        const float qr1 = Qg[lane + 32];

        const int kstart = max(0, q - (WINDOW_ - 1));
        const int cnt = q - kstart + 1;

        float sc[4] = {-1e30f, -1e30f, -1e30f, -1e30f};
#pragma unroll
        for (int blk = 0; blk < 4; blk++) {
            const int lo = blk * 32;
            const int hi = min(cnt, lo + 32);
            for (int ki = lo; ki < hi; ki++) {
                const int j = kstart + ki - ks0;
                float p = qr0 * Ks[j * HD_ + lane] + qr1 * Ks[j * HD_ + lane + 32];
                p += __shfl_xor_sync(0xffffffffu, p, 16);
                p += __shfl_xor_sync(0xffffffffu, p, 8);
                p += __shfl_xor_sync(0xffffffffu, p, 4);
                p += __shfl_xor_sync(0xffffffffu, p, 2);
                p += __shfl_xor_sync(0xffffffffu, p, 1);
                if (lane == (ki - lo)) sc[blk] = p * 0.125f;
            }
        }

        float m = fmaxf(fmaxf(sc[0], sc[1]), fmaxf(sc[2], sc[3]));
#pragma unroll
        for (int o = 16; o > 0; o >>= 1)
            m = fmaxf(m, __shfl_xor_sync(0xffffffffu, m, o));

        float e[4], sum = 0.f;
#pragma unroll
        for (int blk = 0; blk < 4; blk++) {
            e[blk] = expf(sc[blk] - m);
            sum += e[blk];
        }
#pragma unroll
        for (int o = 16; o > 0; o >>= 1)
            sum += __shfl_xor_sync(0xffffffffu, sum, o);
        const float inv = 1.f / sum;

        float acc0 = 0.f, acc1 = 0.f;
#pragma unroll
        for (int blk = 0; blk < 4; blk++) {
            const int lo = blk * 32;
            const int hi = min(cnt, lo + 32);
            const float eb = e[blk];
            for (int ki = lo; ki < hi; ki++) {
                const float p = __shfl_sync(0xffffffffu, eb, ki - lo);
                const int j = kstart + ki - ks0;
                acc0 = fmaf(p, Vs[j * HD_ + lane], acc0);
                acc1 = fmaf(p, Vs[j * HD_ + lane + 32], acc1);
            }
        }

        float* O = g_S + ((size_t)bb * L_ + q) * D_ + h * HD_;
        O[lane]      = acc0 * inv;
        O[lane + 32] = acc1 * inv;
    }
}

// ---------------------------------------------------------------------------
extern "C" void kernel_launch(void* const* d_in, const int* in_sizes, int n_in,
                              void* d_out, int out_size) {
    const float* X = (const float*)d_in[0];
    const float* W[4] = {(const float*)d_in[1], (const float*)d_in[2],
                         (const float*)d_in[3], (const float*)d_in[4]};
    float* out = (float*)d_out;

    float *Q, *K, *V, *S;
    __nv_bfloat16 *Xhi, *Xlo, *Shi, *Slo, *Whi, *Wlo;
    cudaGetSymbolAddress((void**)&Q, g_Q);
    cudaGetSymbolAddress((void**)&K, g_K);
    cudaGetSymbolAddress((void**)&V, g_V);
    cudaGetSymbolAddress((void**)&S, g_S);
    cudaGetSymbolAddress((void**)&Xhi, g_Xhi);
    cudaGetSymbolAddress((void**)&Xlo, g_Xlo);
    cudaGetSymbolAddress((void**)&Shi, g_Shi);
    cudaGetSymbolAddress((void**)&Slo, g_Slo);
    cudaGetSymbolAddress((void**)&Whi, g_Whi);
    cudaGetSymbolAddress((void**)&Wlo, g_Wlo);

    cudaFuncSetAttribute(gemm_mma<0>, cudaFuncAttributeMaxDynamicSharedMemorySize, GSMEM);
    cudaFuncSetAttribute(gemm_mma<1>, cudaFuncAttributeMaxDynamicSharedMemorySize, GSMEM);

    const int xn4 = M_ * D_ / 4;
    split_kernel<<<(xn4 + 255) / 256, 256>>>((const float4*)X,
                                             (__nv_bfloat162*)Xhi, (__nv_bfloat162*)Xlo, xn4);
    const int wn4 = D_ * D_ / 4;
    for (int i = 0; i < 4; i++)
        split_kernel<<<(wn4 + 255) / 256, 256>>>((const float4*)W[i],
            (__nv_bfloat162*)(Whi + (size_t)i * D_ * D_),
            (__nv_bfloat162*)(Wlo + (size_t)i * D_ * D_), wn4);

    const dim3 gg(D_ / TN, M_ / TM);   // (8, 64)
    gemm_mma<1><<<gg, 256, GSMEM>>>(Xhi, Xlo, Whi + 0 * (size_t)D_ * D_,
                                    Wlo + 0 * (size_t)D_ * D_, Q);
    gemm_mma<1><<<gg, 256, GSMEM>>>(Xhi, Xlo, Whi + 1 * (size_t)D_ * D_,
                                    Wlo + 1 * (size_t)D_ * D_, K);
    gemm_mma<1><<<gg, 256, GSMEM>>>(Xhi, Xlo, Whi + 2 * (size_t)D_ * D_,
                                    Wlo + 2 * (size_t)D_ * D_, V);

    const int rt = B_ * H_ * L_ * 32;
    rope_kernel<<<(rt + 255) / 256, 256>>>(Q);
    rope_kernel<<<(rt + 255) / 256, 256>>>(K);

    const int asmem = 2 * KPAD * HD_ * (int)sizeof(float);
    cudaFuncSetAttribute(attn_kernel, cudaFuncAttributeMaxDynamicSharedMemorySize, asmem);
    attn_kernel<<<dim3(L_ / QT, B_ * H_), 256, asmem>>>();

    split_kernel<<<(xn4 + 255) / 256, 256>>>((const float4*)S,
                                             (__nv_bfloat162*)Shi, (__nv_bfloat162*)Slo, xn4);
    gemm_mma<0><<<gg, 256, GSMEM>>>(Shi, Slo, Whi + 3 * (size_t)D_ * D_,
                                    Wlo + 3 * (size_t)D_ * D_, out);
}

// round 4
// speedup vs baseline: 4.5456x; 2.7243x over previous
#include <cuda_runtime.h>
#include <cuda_fp16.h>
#include <math.h>
#include <stdint.h>

// Problem constants
constexpr int B_ = 4, L_ = 2048, D_ = 1024, H_ = 16, HD_ = 64;
constexpr int M_ = B_ * L_;
constexpr int WINDOW_ = 128;

// GEMM tiling
constexpr int TM = 128, TN = 128, KS = 32;
constexpr int NK = D_ / KS;                 // 32 k-steps
constexpr int ROWB = 80;                    // 32 fp16 = 64B -> 80B padded
constexpr int TILE_B = 128 * ROWB;          // 10240
constexpr int STAGE_B = 3 * TILE_B;         // Ahi, Alo, W
constexpr int NSTG = 3;
constexpr int GSMEM = NSTG * STAGE_B;       // 92160

// Attention tiling
constexpr int AQ = 64;                      // q rows per CTA
constexpr int ANK = 192;                    // key window rows (padded)
constexpr int QS_STR = 144, KS_STR = 144, VT_STR = 400;   // bytes per smem row
constexpr int OFF_Q = 0;
constexpr int OFF_K = OFF_Q + AQ * QS_STR;              // 9216
constexpr int OFF_V = OFF_K + ANK * KS_STR;             // 36864
constexpr int ASMEM = OFF_V + HD_ * VT_STR;             // 62464

// Scratch (device globals)
__device__ float g_Q[(size_t)B_ * H_ * L_ * HD_];
__device__ float g_K[(size_t)B_ * H_ * L_ * HD_];
__device__ float g_V[(size_t)B_ * H_ * L_ * HD_];
__device__ float g_S[(size_t)M_ * D_];
__device__ __half g_Xhi[(size_t)M_ * D_];
__device__ __half g_Xlo[(size_t)M_ * D_];
__device__ __half g_Shi[(size_t)M_ * D_];
__device__ __half g_Slo[(size_t)M_ * D_];
__device__ __half g_Wh[4ull * D_ * D_];

__device__ __forceinline__ uint32_t smem_u32(const void* p) {
    uint32_t a;
    asm("{ .reg .u64 t; cvta.to.shared.u64 t, %1; cvt.u32.u64 %0, t; }" : "=r"(a) : "l"(p));
    return a;
}

#define LDSM4(r, addr) \
    asm volatile("ldmatrix.sync.aligned.m8n8.x4.shared.b16 {%0,%1,%2,%3}, [%4];" \
                 : "=r"((r)[0]), "=r"((r)[1]), "=r"((r)[2]), "=r"((r)[3]) : "r"(addr))

#define MMAH(d, a, b0, b1) \
    asm volatile("mma.sync.aligned.m16n8k16.row.col.f32.f16.f16.f32 " \
                 "{%0,%1,%2,%3}, {%4,%5,%6,%7}, {%8,%9}, {%0,%1,%2,%3};" \
                 : "+f"((d)[0]), "+f"((d)[1]), "+f"((d)[2]), "+f"((d)[3]) \
                 : "r"((a)[0]), "r"((a)[1]), "r"((a)[2]), "r"((a)[3]), "r"(b0), "r"(b1))

#define CP_WAIT(n) asm volatile("cp.async.wait_group %0;" :: "n"(n) : "memory")

__device__ __forceinline__ void cp16(uint32_t sa, const void* g) {
    asm volatile("cp.async.cg.shared.global [%0], [%1], 16;" :: "r"(sa), "l"(g));
}

__device__ __forceinline__ uint32_t pack_h2(float lo, float hi) {
    __half2 h = __floats2half2_rn(lo, hi);
    return *(uint32_t*)&h;
}

// Stage one K-chunk: Ahi, Alo, W tiles, each 128 rows x 64B.
__device__ __forceinline__ void cp_stage(char* st, const __half* t0, const __half* t1,
                                         const __half* t2, int ko, int tid) {
    const __half* gp[3] = {t0, t1, t2};
    const uint32_t sb = smem_u32(st);
#pragma unroll
    for (int t = 0; t < 3; t++) {
#pragma unroll
        for (int rep = 0; rep < 2; rep++) {
            const int c = rep * 256 + tid;
            const int row = c >> 2, ch = c & 3;
            cp16(sb + t * TILE_B + row * ROWB + ch * 16,
                 gp[t] + (size_t)row * D_ + ko + ch * 8);
        }
    }
    asm volatile("cp.async.commit_group;" ::: "memory");
}

// ---------------------------------------------------------------------------
// fp16 2-pass GEMM: C = (Ahi + Alo) @ W^T, W rounded to fp16.
// CTA 128x128, K-step 32, 8 warps (2x4), warp tile 64x32, 3-stage pipeline.
// ---------------------------------------------------------------------------
template <int OUT_HEADS>
__global__ void __launch_bounds__(256, 2) gemm_mma(const __half* __restrict__ Ahi,
                                                   const __half* __restrict__ Alo,
                                                   const __half* __restrict__ Wh,
                                                   float* __restrict__ out) {
    extern __shared__ char sm[];
    const int tid = threadIdx.x;
    const int lane = tid & 31, wid = tid >> 5;
    const int mw = wid & 1, nw = wid >> 1;
    const int r0 = blockIdx.y * TM, n0 = blockIdx.x * TN;

    const __half* Ahi_t = Ahi + (size_t)r0 * D_;
    const __half* Alo_t = Alo + (size_t)r0 * D_;
    const __half* W_t   = Wh + (size_t)n0 * D_;

    float acc[4][4][4];
#pragma unroll
    for (int i = 0; i < 4; i++)
#pragma unroll
        for (int j = 0; j < 4; j++)
#pragma unroll
            for (int k = 0; k < 4; k++) acc[i][j][k] = 0.f;

    cp_stage(sm + 0 * STAGE_B, Ahi_t, Alo_t, W_t, 0, tid);
    cp_stage(sm + 1 * STAGE_B, Ahi_t, Alo_t, W_t, KS, tid);

    for (int kc = 0; kc < NK; kc++) {
        const int s = kc % NSTG;
        if (kc + 2 < NK) {
            cp_stage(sm + ((kc + 2) % NSTG) * STAGE_B, Ahi_t, Alo_t, W_t, (kc + 2) * KS, tid);
            CP_WAIT(2);
        } else if (kc + 1 < NK) {
            CP_WAIT(1);
        } else {
            CP_WAIT(0);
        }
        __syncthreads();

        const uint32_t sb = smem_u32(sm + s * STAGE_B);
        const uint32_t lrow = (lane & 15);
        const uint32_t lh = (lane >> 4) * 16;
#pragma unroll
        for (int kt = 0; kt < 2; kt++) {
            uint32_t bw[2][4];
#pragma unroll
            for (int np = 0; np < 2; np++)
                LDSM4(bw[np], sb + 2 * TILE_B + (nw * 32 + np * 16 + lrow) * ROWB + kt * 32 + lh);
#pragma unroll
            for (int mt = 0; mt < 4; mt++) {
                uint32_t ah[4], al[4];
                const uint32_t aa = sb + (mw * 64 + mt * 16 + lrow) * ROWB + kt * 32 + lh;
                LDSM4(ah, aa);
                LDSM4(al, aa + TILE_B);
#pragma unroll
                for (int nt = 0; nt < 4; nt++) {
                    const uint32_t b0 = bw[nt >> 1][nt & 1], b1 = bw[nt >> 1][(nt & 1) + 2];
                    MMAH(acc[mt][nt], ah, b0, b1);
                    MMAH(acc[mt][nt], al, b0, b1);
                }
            }
        }
        __syncthreads();
    }

#pragma unroll
    for (int mt = 0; mt < 4; mt++) {
#pragma unroll
        for (int nt = 0; nt < 4; nt++) {
            const int row = r0 + mw * 64 + mt * 16 + (lane >> 2);
            const int col = n0 + nw * 32 + nt * 8 + 2 * (lane & 3);
            float *d0, *d1;
            if (OUT_HEADS) {
                const int h = col >> 6, dd = col & 63;
                const int bb0 = row >> 11, l0 = row & (L_ - 1);
                d0 = out + (((size_t)bb0 * H_ + h) * L_ + l0) * HD_ + dd;
                const int r8 = row + 8;
                const int bb1 = r8 >> 11, l1 = r8 & (L_ - 1);
                d1 = out + (((size_t)bb1 * H_ + h) * L_ + l1) * HD_ + dd;
            } else {
                d0 = out + (size_t)row * D_ + col;
                d1 = out + (size_t)(row + 8) * D_ + col;
            }
            *(float2*)d0 = make_float2(acc[mt][nt][0], acc[mt][nt][1]);
            *(float2*)d1 = make_float2(acc[mt][nt][2], acc[mt][nt][3]);
        }
    }
}

// ---------------------------------------------------------------------------
// fp32 -> fp16 hi/lo split
// ---------------------------------------------------------------------------
__global__ void split_kernel(const float4* __restrict__ x,
                             __half2* __restrict__ hi, __half2* __restrict__ lo, int n4) {
    const int i = blockIdx.x * blockDim.x + threadIdx.x;
    if (i >= n4) return;
    const float4 v = x[i];
    const __half h0 = __float2half_rn(v.x), h1 = __float2half_rn(v.y);
    const __half h2 = __float2half_rn(v.z), h3 = __float2half_rn(v.w);
    hi[2 * i]     = __halves2half2(h0, h1);
    hi[2 * i + 1] = __halves2half2(h2, h3);
    lo[2 * i]     = __floats2half2_rn(v.x - __half2float(h0), v.y - __half2float(h1));
    lo[2 * i + 1] = __floats2half2_rn(v.z - __half2float(h2), v.w - __half2float(h3));
}

// fp32 -> fp16 round (weights)
__global__ void cvt_kernel(const float4* __restrict__ x, __half2* __restrict__ o, int n4) {
    const int i = blockIdx.x * blockDim.x + threadIdx.x;
    if (i >= n4) return;
    const float4 v = x[i];
    o[2 * i]     = __floats2half2_rn(v.x, v.y);
    o[2 * i + 1] = __floats2half2_rn(v.z, v.w);
}

// ---------------------------------------------------------------------------
// RoPE in-place over [B,H,L,hd] (fp32)
// ---------------------------------------------------------------------------
__global__ void rope_kernel(float* __restrict__ x) {
    const int i = blockIdx.x * blockDim.x + threadIdx.x;
    if (i >= B_ * H_ * L_ * 32) return;
    const int j = i & 31;
    const int row = i >> 5;
    const int l = row & (L_ - 1);
    const float invf = expf(-(float)j * 0.28782313662425575f);
    float s, c;
    sincosf((float)l * invf, &s, &c);
    const size_t base = (size_t)row * HD_;
    const float x0 = x[base + j];
    const float x1 = x[base + j + 32];
    x[base + j]      = x0 * c - x1 * s;
    x[base + j + 32] = x1 * c + x0 * s;
}

// ---------------------------------------------------------------------------
// Sliding-window attention via mma.sync (flash-style, single pass).
// CTA = (b,h) x 64-query tile; 4 warps, each owns 16 q rows x all 192 keys.
// ---------------------------------------------------------------------------
__global__ void __launch_bounds__(128) attn_mma() {
    extern __shared__ char sm[];
    const uint32_t sb = smem_u32(sm);
    const int tid = threadIdx.x;
    const int lane = tid & 31, w = tid >> 5;
    const int bh = blockIdx.y;
    const int q0 = blockIdx.x * AQ;
    const int ks0 = q0 - (WINDOW_ - 1);
    const int jmin = (q0 < WINDOW_ - 1) ? (WINDOW_ - 1 - q0) : 0;

    // --- load & convert Q (64 x 64 fp16) ---
    const float* Qg = g_Q + ((size_t)bh * L_ + q0) * HD_;
    for (int idx = tid; idx < AQ * 16; idx += 128) {
        const int row = idx >> 4, c4 = idx & 15;
        const float4 v = *(const float4*)(Qg + (size_t)row * HD_ + c4 * 4);
        char* p = sm + OFF_Q + row * QS_STR + c4 * 8;
        *(__half2*)p       = __floats2half2_rn(v.x, v.y);
        *(__half2*)(p + 4) = __floats2half2_rn(v.z, v.w);
    }
    // --- load & convert K (192 x 64 fp16), zero-fill OOB rows ---
    const float* Kg = g_K + (size_t)bh * L_ * HD_;
    for (int idx = tid; idx < ANK * 16; idx += 128) {
        const int row = idx >> 4, c4 = idx & 15;
        const int kg = ks0 + row;
        float4 v = make_float4(0.f, 0.f, 0.f, 0.f);
        if (kg >= 0 && kg < L_) v = *(const float4*)(Kg + (size_t)kg * HD_ + c4 * 4);
        char* p = sm + OFF_K + row * KS_STR + c4 * 8;
        *(__half2*)p       = __floats2half2_rn(v.x, v.y);
        *(__half2*)(p + 4) = __floats2half2_rn(v.z, v.w);
    }
    // --- load V transposed: Vt[d][key] fp16 ---
    const float* Vg = g_V + (size_t)bh * L_ * HD_;
    for (int idx = tid; idx < ANK * 16; idx += 128) {
        const int row = idx >> 4, c4 = idx & 15;
        const int kg = ks0 + row;
        float4 v = make_float4(0.f, 0.f, 0.f, 0.f);
        if (kg >= 0 && kg < L_) v = *(const float4*)(Vg + (size_t)kg * HD_ + c4 * 4);
        const float vv[4] = {v.x, v.y, v.z, v.w};
#pragma unroll
        for (int i = 0; i < 4; i++)
            *(__half*)(sm + OFF_V + (c4 * 4 + i) * VT_STR + row * 2) = __float2half_rn(vv[i]);
    }
    __syncthreads();

    // --- S = Q K^T : 24 n8 fragments per warp ---
    float sac[24][4];
#pragma unroll
    for (int f = 0; f < 24; f++)
#pragma unroll
        for (int k = 0; k < 4; k++) sac[f][k] = 0.f;

    const uint32_t lrow = (lane & 15);
    const uint32_t lh = (lane >> 4) * 16;
#pragma unroll
    for (int kt = 0; kt < 4; kt++) {
        uint32_t aq[4];
        LDSM4(aq, sb + OFF_Q + (16 * w + lrow) * QS_STR + kt * 32 + lh);
#pragma unroll
        for (int nb = 0; nb < 12; nb++) {
            uint32_t bk[4];
            LDSM4(bk, sb + OFF_K + (nb * 16 + lrow) * KS_STR + kt * 32 + lh);
            MMAH(sac[2 * nb],     aq, bk[0], bk[2]);
            MMAH(sac[2 * nb + 1], aq, bk[1], bk[3]);
        }
    }

    // --- mask (band j-i in [0,127] and j >= jmin) + softmax, register-resident ---
    const int i1 = 16 * w + (lane >> 2);
    const int i2 = i1 + 8;
    const int cq = (lane & 3) * 2;
    constexpr float SCALE = 0.125f;
    float m1 = -1e30f, m2 = -1e30f;
#pragma unroll
    for (int f = 0; f < 24; f++) {
        const int j0 = 8 * f + cq, j1 = j0 + 1;
        const bool k00 = ((unsigned)(j0 - i1) < (unsigned)WINDOW_) && j0 >= jmin;
        const bool k01 = ((unsigned)(j1 - i1) < (unsigned)WINDOW_) && j1 >= jmin;
        const bool k10 = ((unsigned)(j0 - i2) < (unsigned)WINDOW_) && j0 >= jmin;
        const bool k11 = ((unsigned)(j1 - i2) < (unsigned)WINDOW_) && j1 >= jmin;
        sac[f][0] = k00 ? sac[f][0] * SCALE : -1e30f;
        sac[f][1] = k01 ? sac[f][1] * SCALE : -1e30f;
        sac[f][2] = k10 ? sac[f][2] * SCALE : -1e30f;
        sac[f][3] = k11 ? sac[f][3] * SCALE : -1e30f;
        m1 = fmaxf(m1, fmaxf(sac[f][0], sac[f][1]));
        m2 = fmaxf(m2, fmaxf(sac[f][2], sac[f][3]));
    }
    m1 = fmaxf(m1, __shfl_xor_sync(0xffffffffu, m1, 1));
    m1 = fmaxf(m1, __shfl_xor_sync(0xffffffffu, m1, 2));
    m2 = fmaxf(m2, __shfl_xor_sync(0xffffffffu, m2, 1));
    m2 = fmaxf(m2, __shfl_xor_sync(0xffffffffu, m2, 2));

    float l1 = 0.f, l2 = 0.f;
#pragma unroll
    for (int f = 0; f < 24; f++) {
        sac[f][0] = __expf(sac[f][0] - m1);
        sac[f][1] = __expf(sac[f][1] - m1);
        sac[f][2] = __expf(sac[f][2] - m2);
        sac[f][3] = __expf(sac[f][3] - m2);
        l1 += sac[f][0] + sac[f][1];
        l2 += sac[f][2] + sac[f][3];
    }
    l1 += __shfl_xor_sync(0xffffffffu, l1, 1);
    l1 += __shfl_xor_sync(0xffffffffu, l1, 2);
    l2 += __shfl_xor_sync(0xffffffffu, l2, 1);
    l2 += __shfl_xor_sync(0xffffffffu, l2, 2);

    // --- O = P V : S-fragments map directly onto A-fragments ---
    float oac[8][4];
#pragma unroll
    for (int f = 0; f < 8; f++)
#pragma unroll
        for (int k = 0; k < 4; k++) oac[f][k] = 0.f;

#pragma unroll
    for (int kb = 0; kb < 12; kb++) {
        uint32_t pa[4];
        pa[0] = pack_h2(sac[2 * kb][0],     sac[2 * kb][1]);
        pa[1] = pack_h2(sac[2 * kb][2],     sac[2 * kb][3]);
        pa[2] = pack_h2(sac[2 * kb + 1][0], sac[2 * kb + 1][1]);
        pa[3] = pack_h2(sac[2 * kb + 1][2], sac[2 * kb + 1][3]);
#pragma unroll
        for (int db = 0; db < 4; db++) {
            uint32_t bv[4];
            LDSM4(bv, sb + OFF_V + (db * 16 + lrow) * VT_STR + kb * 32 + lh);
            MMAH(oac[2 * db],     pa, bv[0], bv[2]);
            MMAH(oac[2 * db + 1], pa, bv[1], bv[3]);
        }
    }

    // --- epilogue: normalize & scatter to g_S [B,L,D] ---
    const float inv1 = 1.f / l1, inv2 = 1.f / l2;
    const int bb = bh >> 4, h = bh & (H_ - 1);
    const int q1 = q0 + i1, q2 = q0 + i2;
    float* o1 = g_S + ((size_t)bb * L_ + q1) * D_ + h * HD_;
    float* o2 = g_S + ((size_t)bb * L_ + q2) * D_ + h * HD_;
#pragma unroll
    for (int f = 0; f < 8; f++) {
        const int d0 = 8 * f + cq;
        *(float2*)(o1 + d0) = make_float2(oac[f][0] * inv1, oac[f][1] * inv1);
        *(float2*)(o2 + d0) = make_float2(oac[f][2] * inv2, oac[f][3] * inv2);
    }
}

// ---------------------------------------------------------------------------
extern "C" void kernel_launch(void* const* d_in, const int* in_sizes, int n_in,
                              void* d_out, int out_size) {
    const float* X = (const float*)d_in[0];
    const float* W[4] = {(const float*)d_in[1], (const float*)d_in[2],
                         (const float*)d_in[3], (const float*)d_in[4]};
    float* out = (float*)d_out;

    float *Q, *K, *V, *S;
    __half *Xhi, *Xlo, *Shi, *Slo, *Wh;
    cudaGetSymbolAddress((void**)&Q, g_Q);
    cudaGetSymbolAddress((void**)&K, g_K);
    cudaGetSymbolAddress((void**)&V, g_V);
    cudaGetSymbolAddress((void**)&S, g_S);
    cudaGetSymbolAddress((void**)&Xhi, g_Xhi);
    cudaGetSymbolAddress((void**)&Xlo, g_Xlo);
    cudaGetSymbolAddress((void**)&Shi, g_Shi);
    cudaGetSymbolAddress((void**)&Slo, g_Slo);
    cudaGetSymbolAddress((void**)&Wh, g_Wh);

    cudaFuncSetAttribute(gemm_mma<0>, cudaFuncAttributeMaxDynamicSharedMemorySize, GSMEM);
    cudaFuncSetAttribute(gemm_mma<1>, cudaFuncAttributeMaxDynamicSharedMemorySize, GSMEM);
    cudaFuncSetAttribute(attn_mma, cudaFuncAttributeMaxDynamicSharedMemorySize, ASMEM);

    const int xn4 = M_ * D_ / 4;
    split_kernel<<<(xn4 + 255) / 256, 256>>>((const float4*)X, (__half2*)Xhi, (__half2*)Xlo, xn4);
    const int wn4 = D_ * D_ / 4;
    for (int i = 0; i < 4; i++)
        cvt_kernel<<<(wn4 + 255) / 256, 256>>>((const float4*)W[i],
                                               (__half2*)(Wh + (size_t)i * D_ * D_), wn4);

    const dim3 gg(D_ / TN, M_ / TM);   // (8, 64)
    gemm_mma<1><<<gg, 256, GSMEM>>>(Xhi, Xlo, Wh + 0 * (size_t)D_ * D_, Q);
    gemm_mma<1><<<gg, 256, GSMEM>>>(Xhi, Xlo, Wh + 1 * (size_t)D_ * D_, K);
    gemm_mma<1><<<gg, 256, GSMEM>>>(Xhi, Xlo, Wh + 2 * (size_t)D_ * D_, V);

    const int rt = B_ * H_ * L_ * 32;
    rope_kernel<<<(rt + 255) / 256, 256>>>(Q);
    rope_kernel<<<(rt + 255) / 256, 256>>>(K);

    attn_mma<<<dim3(L_ / AQ, B_ * H_), 128, ASMEM>>>();

    split_kernel<<<(xn4 + 255) / 256, 256>>>((const float4*)S, (__half2*)Shi, (__half2*)Slo, xn4);
    gemm_mma<0><<<gg, 256, GSMEM>>>(Shi, Slo, Wh + 3 * (size_t)D_ * D_, out);
}

// round 5
// speedup vs baseline: 4.8574x; 1.0686x over previous
#include <cuda_runtime.h>
#include <cuda_fp16.h>
#include <math.h>
#include <stdint.h>

// Problem constants
constexpr int B_ = 4, L_ = 2048, D_ = 1024, H_ = 16, HD_ = 64;
constexpr int M_ = B_ * L_;
constexpr int WINDOW_ = 128;

// GEMM tiling
constexpr int TM = 128, TN = 128, KS = 32;
constexpr int NK = D_ / KS;
constexpr int ROWB = 80;
constexpr int TILE_B = 128 * ROWB;
constexpr int STAGE_B = 3 * TILE_B;
constexpr int NSTG = 3;
constexpr int GSMEM = NSTG * STAGE_B;       // 92160

// Attention tiling
constexpr int AQ = 64;
constexpr int ANK = 192;
constexpr int ASTR = 144;                   // 64 halves = 128B -> 144B padded
constexpr int OFF_Q = 0;
constexpr int OFF_K = OFF_Q + AQ * ASTR;    // 9216
constexpr int OFF_V = OFF_K + ANK * ASTR;   // 36864
constexpr int ASMEM = OFF_V + ANK * ASTR;   // 64512

// Scratch (device globals)
__device__ __half g_Qh[(size_t)B_ * H_ * L_ * HD_];
__device__ __half g_Kh[(size_t)B_ * H_ * L_ * HD_];
__device__ __half g_Vh[(size_t)B_ * H_ * L_ * HD_];
__device__ __half g_Shi[(size_t)M_ * D_];
__device__ __half g_Slo[(size_t)M_ * D_];
__device__ __half g_Xhi[(size_t)M_ * D_];
__device__ __half g_Xlo[(size_t)M_ * D_];
__device__ __half g_Wh[4ull * D_ * D_];
__device__ float g_cos[L_ * 32];
__device__ float g_sin[L_ * 32];

__device__ __forceinline__ uint32_t smem_u32(const void* p) {
    uint32_t a;
    asm("{ .reg .u64 t; cvta.to.shared.u64 t, %1; cvt.u32.u64 %0, t; }" : "=r"(a) : "l"(p));
    return a;
}

#define LDSM4(r, addr) \
    asm volatile("ldmatrix.sync.aligned.m8n8.x4.shared.b16 {%0,%1,%2,%3}, [%4];" \
                 : "=r"((r)[0]), "=r"((r)[1]), "=r"((r)[2]), "=r"((r)[3]) : "r"(addr))

#define LDSM4T(r, addr) \
    asm volatile("ldmatrix.sync.aligned.m8n8.x4.trans.shared.b16 {%0,%1,%2,%3}, [%4];" \
                 : "=r"((r)[0]), "=r"((r)[1]), "=r"((r)[2]), "=r"((r)[3]) : "r"(addr))

#define MMAH(d, a, b0, b1) \
    asm volatile("mma.sync.aligned.m16n8k16.row.col.f32.f16.f16.f32 " \
                 "{%0,%1,%2,%3}, {%4,%5,%6,%7}, {%8,%9}, {%0,%1,%2,%3};" \
                 : "+f"((d)[0]), "+f"((d)[1]), "+f"((d)[2]), "+f"((d)[3]) \
                 : "r"((a)[0]), "r"((a)[1]), "r"((a)[2]), "r"((a)[3]), "r"(b0), "r"(b1))

#define CP_WAIT(n) asm volatile("cp.async.wait_group %0;" :: "n"(n) : "memory")

__device__ __forceinline__ void cp16(uint32_t sa, const void* g) {
    asm volatile("cp.async.cg.shared.global [%0], [%1], 16;" :: "r"(sa), "l"(g));
}

__device__ __forceinline__ uint32_t pack_h2(float lo, float hi) {
    __half2 h = __floats2half2_rn(lo, hi);
    return *(uint32_t*)&h;
}

__device__ __forceinline__ void cp_stage(char* st, const __half* t0, const __half* t1,
                                         const __half* t2, int ko, int tid) {
    const __half* gp[3] = {t0, t1, t2};
    const uint32_t sb = smem_u32(st);
#pragma unroll
    for (int t = 0; t < 3; t++) {
#pragma unroll
        for (int rep = 0; rep < 2; rep++) {
            const int c = rep * 256 + tid;
            const int row = c >> 2, ch = c & 3;
            cp16(sb + t * TILE_B + row * ROWB + ch * 16,
                 gp[t] + (size_t)row * D_ + ko + ch * 8);
        }
    }
    asm volatile("cp.async.commit_group;" ::: "memory");
}

// ---------------------------------------------------------------------------
// fp16 2-pass GEMM: C = (Ahi + Alo) @ W^T.
// MODE 0: fp32 row-major out.  MODE 1: fp16 head-scatter out [B,H,L,hd].
// ---------------------------------------------------------------------------
template <int MODE>
__global__ void __launch_bounds__(256, 2) gemm_mma(const __half* __restrict__ Ahi,
                                                   const __half* __restrict__ Alo,
                                                   const __half* __restrict__ Wh,
                                                   void* __restrict__ outv) {
    extern __shared__ char sm[];
    const int tid = threadIdx.x;
    const int lane = tid & 31, wid = tid >> 5;
    const int mw = wid & 1, nw = wid >> 1;
    const int r0 = blockIdx.y * TM, n0 = blockIdx.x * TN;

    const __half* Ahi_t = Ahi + (size_t)r0 * D_;
    const __half* Alo_t = Alo + (size_t)r0 * D_;
    const __half* W_t   = Wh + (size_t)n0 * D_;

    float acc[4][4][4];
#pragma unroll
    for (int i = 0; i < 4; i++)
#pragma unroll
        for (int j = 0; j < 4; j++)
#pragma unroll
            for (int k = 0; k < 4; k++) acc[i][j][k] = 0.f;

    cp_stage(sm + 0 * STAGE_B, Ahi_t, Alo_t, W_t, 0, tid);
    cp_stage(sm + 1 * STAGE_B, Ahi_t, Alo_t, W_t, KS, tid);

    for (int kc = 0; kc < NK; kc++) {
        const int s = kc % NSTG;
        if (kc + 2 < NK) {
            cp_stage(sm + ((kc + 2) % NSTG) * STAGE_B, Ahi_t, Alo_t, W_t, (kc + 2) * KS, tid);
            CP_WAIT(2);
        } else if (kc + 1 < NK) {
            CP_WAIT(1);
        } else {
            CP_WAIT(0);
        }
        __syncthreads();

        const uint32_t sb = smem_u32(sm + s * STAGE_B);
        const uint32_t lrow = (lane & 15);
        const uint32_t lh = (lane >> 4) * 16;
#pragma unroll
        for (int kt = 0; kt < 2; kt++) {
            uint32_t bw[2][4];
#pragma unroll
            for (int np = 0; np < 2; np++)
                LDSM4(bw[np], sb + 2 * TILE_B + (nw * 32 + np * 16 + lrow) * ROWB + kt * 32 + lh);
#pragma unroll
            for (int mt = 0; mt < 4; mt++) {
                uint32_t ah[4], al[4];
                const uint32_t aa = sb + (mw * 64 + mt * 16 + lrow) * ROWB + kt * 32 + lh;
                LDSM4(ah, aa);
                LDSM4(al, aa + TILE_B);
#pragma unroll
                for (int nt = 0; nt < 4; nt++) {
                    const uint32_t b0 = bw[nt >> 1][nt & 1], b1 = bw[nt >> 1][(nt & 1) + 2];
                    MMAH(acc[mt][nt], ah, b0, b1);
                    MMAH(acc[mt][nt], al, b0, b1);
                }
            }
        }
        __syncthreads();
    }

#pragma unroll
    for (int mt = 0; mt < 4; mt++) {
#pragma unroll
        for (int nt = 0; nt < 4; nt++) {
            const int row = r0 + mw * 64 + mt * 16 + (lane >> 2);
            const int col = n0 + nw * 32 + nt * 8 + 2 * (lane & 3);
            if (MODE == 1) {
                __half* out = (__half*)outv;
                const int h = col >> 6, dd = col & 63;
                const int bb0 = row >> 11, l0 = row & (L_ - 1);
                const int r8 = row + 8;
                const int bb1 = r8 >> 11, l1 = r8 & (L_ - 1);
                *(__half2*)(out + (((size_t)bb0 * H_ + h) * L_ + l0) * HD_ + dd) =
                    __floats2half2_rn(acc[mt][nt][0], acc[mt][nt][1]);
                *(__half2*)(out + (((size_t)bb1 * H_ + h) * L_ + l1) * HD_ + dd) =
                    __floats2half2_rn(acc[mt][nt][2], acc[mt][nt][3]);
            } else {
                float* out = (float*)outv;
                *(float2*)(out + (size_t)row * D_ + col) =
                    make_float2(acc[mt][nt][0], acc[mt][nt][1]);
                *(float2*)(out + (size_t)(row + 8) * D_ + col) =
                    make_float2(acc[mt][nt][2], acc[mt][nt][3]);
            }
        }
    }
}

// ---------------------------------------------------------------------------
// fp32 -> fp16 hi/lo split (X)
// ---------------------------------------------------------------------------
__global__ void split_kernel(const float4* __restrict__ x,
                             __half2* __restrict__ hi, __half2* __restrict__ lo, int n4) {
    const int i = blockIdx.x * blockDim.x + threadIdx.x;
    if (i >= n4) return;
    const float4 v = x[i];
    const __half h0 = __float2half_rn(v.x), h1 = __float2half_rn(v.y);
    const __half h2 = __float2half_rn(v.z), h3 = __float2half_rn(v.w);
    hi[2 * i]     = __halves2half2(h0, h1);
    hi[2 * i + 1] = __halves2half2(h2, h3);
    lo[2 * i]     = __floats2half2_rn(v.x - __half2float(h0), v.y - __half2float(h1));
    lo[2 * i + 1] = __floats2half2_rn(v.z - __half2float(h2), v.w - __half2float(h3));
}

// fp32 -> fp16 round (weights)
__global__ void cvt_kernel(const float4* __restrict__ x, __half2* __restrict__ o, int n4) {
    const int i = blockIdx.x * blockDim.x + threadIdx.x;
    if (i >= n4) return;
    const float4 v = x[i];
    o[2 * i]     = __floats2half2_rn(v.x, v.y);
    o[2 * i + 1] = __floats2half2_rn(v.z, v.w);
}

// RoPE cos/sin table [L, 32]
__global__ void rope_tab_kernel() {
    const int i = blockIdx.x * blockDim.x + threadIdx.x;
    if (i >= L_ * 32) return;
    const int j = i & 31, l = i >> 5;
    const float invf = expf(-(float)j * 0.28782313662425575f);
    float s, c;
    sincosf((float)l * invf, &s, &c);
    g_cos[i] = c;
    g_sin[i] = s;
}

// ---------------------------------------------------------------------------
// Sliding-window attention: fp16 inputs, RoPE fused at load, mma.sync core.
// CTA = (b,h) x 64-query tile; 4 warps, each 16 q rows x 192 keys.
// Epilogue writes fp16 hi/lo split of output directly.
// ---------------------------------------------------------------------------
__global__ void __launch_bounds__(128) attn_mma() {
    extern __shared__ char sm[];
    const uint32_t sb = smem_u32(sm);
    const int tid = threadIdx.x;
    const int lane = tid & 31, w = tid >> 5;
    const int bh = blockIdx.y;
    const int q0 = blockIdx.x * AQ;
    const int ks0 = q0 - (WINDOW_ - 1);
    const int jmin = (q0 < WINDOW_ - 1) ? (WINDOW_ - 1 - q0) : 0;

    // --- Q: load fp16, apply RoPE, store to smem ---
    const __half* Qg = g_Qh + ((size_t)bh * L_ + q0) * HD_;
    for (int idx = tid; idx < AQ * 8; idx += 128) {
        const int row = idx >> 3, d0 = (idx & 7) * 4;
        const __half* qp = Qg + (size_t)row * HD_ + d0;
        const uint2 ua = *(const uint2*)qp;
        const uint2 ub = *(const uint2*)(qp + 32);
        const __half2* ha = (const __half2*)&ua;
        const __half2* hb = (const __half2*)&ub;
        const float a[4] = {__low2float(ha[0]), __high2float(ha[0]),
                            __low2float(ha[1]), __high2float(ha[1])};
        const float b[4] = {__low2float(hb[0]), __high2float(hb[0]),
                            __low2float(hb[1]), __high2float(hb[1])};
        const float4 cc = *(const float4*)(g_cos + (q0 + row) * 32 + d0);
        const float4 ss = *(const float4*)(g_sin + (q0 + row) * 32 + d0);
        const float c[4] = {cc.x, cc.y, cc.z, cc.w};
        const float s[4] = {ss.x, ss.y, ss.z, ss.w};
        char* p = sm + OFF_Q + row * ASTR + d0 * 2;
#pragma unroll
        for (int e = 0; e < 4; e += 2) {
            *(__half2*)(p + e * 2) = __floats2half2_rn(a[e] * c[e] - b[e] * s[e],
                                                       a[e + 1] * c[e + 1] - b[e + 1] * s[e + 1]);
            *(__half2*)(p + 64 + e * 2) = __floats2half2_rn(b[e] * c[e] + a[e] * s[e],
                                                            b[e + 1] * c[e + 1] + a[e + 1] * s[e + 1]);
        }
    }
    // --- K: same with window offset, zero-fill OOB ---
    const __half* Kg = g_Kh + (size_t)bh * L_ * HD_;
    for (int idx = tid; idx < ANK * 8; idx += 128) {
        const int row = idx >> 3, d0 = (idx & 7) * 4;
        const int kg = ks0 + row;
        char* p = sm + OFF_K + row * ASTR + d0 * 2;
        if (kg < 0) {
            *(uint2*)p = make_uint2(0, 0);
            *(uint2*)(p + 64) = make_uint2(0, 0);
            continue;
        }
        const __half* kp = Kg + (size_t)kg * HD_ + d0;
        const uint2 ua = *(const uint2*)kp;
        const uint2 ub = *(const uint2*)(kp + 32);
        const __half2* ha = (const __half2*)&ua;
        const __half2* hb = (const __half2*)&ub;
        const float a[4] = {__low2float(ha[0]), __high2float(ha[0]),
                            __low2float(ha[1]), __high2float(ha[1])};
        const float b[4] = {__low2float(hb[0]), __high2float(hb[0]),
                            __low2float(hb[1]), __high2float(hb[1])};
        const float4 cc = *(const float4*)(g_cos + kg * 32 + d0);
        const float4 ss = *(const float4*)(g_sin + kg * 32 + d0);
        const float c[4] = {cc.x, cc.y, cc.z, cc.w};
        const float s[4] = {ss.x, ss.y, ss.z, ss.w};
#pragma unroll
        for (int e = 0; e < 4; e += 2) {
            *(__half2*)(p + e * 2) = __floats2half2_rn(a[e] * c[e] - b[e] * s[e],
                                                       a[e + 1] * c[e + 1] - b[e + 1] * s[e + 1]);
            *(__half2*)(p + 64 + e * 2) = __floats2half2_rn(b[e] * c[e] + a[e] * s[e],
                                                            b[e + 1] * c[e + 1] + a[e + 1] * s[e + 1]);
        }
    }
    // --- V: straight fp16 copy (row-major, ldmatrix.trans later) ---
    const __half* Vg = g_Vh + (size_t)bh * L_ * HD_;
    for (int idx = tid; idx < ANK * 8; idx += 128) {
        const int row = idx >> 3, c8 = idx & 7;
        const int kg = ks0 + row;
        uint4 v = make_uint4(0, 0, 0, 0);
        if (kg >= 0) v = *(const uint4*)(Vg + (size_t)kg * HD_ + c8 * 8);
        *(uint4*)(sm + OFF_V + row * ASTR + c8 * 16) = v;
    }
    __syncthreads();

    // --- S = Q K^T ---
    float sac[24][4];
#pragma unroll
    for (int f = 0; f < 24; f++)
#pragma unroll
        for (int k = 0; k < 4; k++) sac[f][k] = 0.f;

    const uint32_t lrow = (lane & 15);
    const uint32_t lh = (lane >> 4) * 16;
#pragma unroll
    for (int kt = 0; kt < 4; kt++) {
        uint32_t aq[4];
        LDSM4(aq, sb + OFF_Q + (16 * w + lrow) * ASTR + kt * 32 + lh);
#pragma unroll
        for (int nb = 0; nb < 12; nb++) {
            uint32_t bk[4];
            LDSM4(bk, sb + OFF_K + (nb * 16 + lrow) * ASTR + kt * 32 + lh);
            MMAH(sac[2 * nb],     aq, bk[0], bk[2]);
            MMAH(sac[2 * nb + 1], aq, bk[1], bk[3]);
        }
    }

    // --- mask + softmax (register-resident) ---
    const int i1 = 16 * w + (lane >> 2);
    const int i2 = i1 + 8;
    const int cq = (lane & 3) * 2;
    constexpr float SCALE = 0.125f;
    float m1 = -1e30f, m2 = -1e30f;
#pragma unroll
    for (int f = 0; f < 24; f++) {
        const int j0 = 8 * f + cq, j1 = j0 + 1;
        const bool k00 = ((unsigned)(j0 - i1) < (unsigned)WINDOW_) && j0 >= jmin;
        const bool k01 = ((unsigned)(j1 - i1) < (unsigned)WINDOW_) && j1 >= jmin;
        const bool k10 = ((unsigned)(j0 - i2) < (unsigned)WINDOW_) && j0 >= jmin;
        const bool k11 = ((unsigned)(j1 - i2) < (unsigned)WINDOW_) && j1 >= jmin;
        sac[f][0] = k00 ? sac[f][0] * SCALE : -1e30f;
        sac[f][1] = k01 ? sac[f][1] * SCALE : -1e30f;
        sac[f][2] = k10 ? sac[f][2] * SCALE : -1e30f;
        sac[f][3] = k11 ? sac[f][3] * SCALE : -1e30f;
        m1 = fmaxf(m1, fmaxf(sac[f][0], sac[f][1]));
        m2 = fmaxf(m2, fmaxf(sac[f][2], sac[f][3]));
    }
    m1 = fmaxf(m1, __shfl_xor_sync(0xffffffffu, m1, 1));
    m1 = fmaxf(m1, __shfl_xor_sync(0xffffffffu, m1, 2));
    m2 = fmaxf(m2, __shfl_xor_sync(0xffffffffu, m2, 1));
    m2 = fmaxf(m2, __shfl_xor_sync(0xffffffffu, m2, 2));

    float l1 = 0.f, l2 = 0.f;
#pragma unroll
    for (int f = 0; f < 24; f++) {
        sac[f][0] = __expf(sac[f][0] - m1);
        sac[f][1] = __expf(sac[f][1] - m1);
        sac[f][2] = __expf(sac[f][2] - m2);
        sac[f][3] = __expf(sac[f][3] - m2);
        l1 += sac[f][0] + sac[f][1];
        l2 += sac[f][2] + sac[f][3];
    }
    l1 += __shfl_xor_sync(0xffffffffu, l1, 1);
    l1 += __shfl_xor_sync(0xffffffffu, l1, 2);
    l2 += __shfl_xor_sync(0xffffffffu, l2, 1);
    l2 += __shfl_xor_sync(0xffffffffu, l2, 2);

    // --- O = P V (V via ldmatrix.trans) ---
    float oac[8][4];
#pragma unroll
    for (int f = 0; f < 8; f++)
#pragma unroll
        for (int k = 0; k < 4; k++) oac[f][k] = 0.f;

#pragma unroll
    for (int kb = 0; kb < 12; kb++) {
        uint32_t pa[4];
        pa[0] = pack_h2(sac[2 * kb][0],     sac[2 * kb][1]);
        pa[1] = pack_h2(sac[2 * kb][2],     sac[2 * kb][3]);
        pa[2] = pack_h2(sac[2 * kb + 1][0], sac[2 * kb + 1][1]);
        pa[3] = pack_h2(sac[2 * kb + 1][2], sac[2 * kb + 1][3]);
#pragma unroll
        for (int db = 0; db < 4; db++) {
            uint32_t bv[4];
            LDSM4T(bv, sb + OFF_V + (kb * 16 + lrow) * ASTR + db * 32 + lh);
            MMAH(oac[2 * db],     pa, bv[0], bv[1]);
            MMAH(oac[2 * db + 1], pa, bv[2], bv[3]);
        }
    }

    // --- epilogue: normalize, fp16 hi/lo split, write Shi/Slo [B,L,D] ---
    const float inv1 = 1.f / l1, inv2 = 1.f / l2;
    const int bb = bh >> 4, h = bh & (H_ - 1);
    const size_t off1 = ((size_t)bb * L_ + q0 + i1) * D_ + h * HD_;
    const size_t off2 = ((size_t)bb * L_ + q0 + i2) * D_ + h * HD_;
#pragma unroll
    for (int f = 0; f < 8; f++) {
        const int d0 = 8 * f + cq;
        const float v10 = oac[f][0] * inv1, v11 = oac[f][1] * inv1;
        const float v20 = oac[f][2] * inv2, v21 = oac[f][3] * inv2;
        const __half h10 = __float2half_rn(v10), h11 = __float2half_rn(v11);
        const __half h20 = __float2half_rn(v20), h21 = __float2half_rn(v21);
        *(__half2*)(g_Shi + off1 + d0) = __halves2half2(h10, h11);
        *(__half2*)(g_Shi + off2 + d0) = __halves2half2(h20, h21);
        *(__half2*)(g_Slo + off1 + d0) =
            __floats2half2_rn(v10 - __half2float(h10), v11 - __half2float(h11));
        *(__half2*)(g_Slo + off2 + d0) =
            __floats2half2_rn(v20 - __half2float(h20), v21 - __half2float(h21));
    }
}

// ---------------------------------------------------------------------------
extern "C" void kernel_launch(void* const* d_in, const int* in_sizes, int n_in,
                              void* d_out, int out_size) {
    const float* X = (const float*)d_in[0];
    const float* W[4] = {(const float*)d_in[1], (const float*)d_in[2],
                         (const float*)d_in[3], (const float*)d_in[4]};
    float* out = (float*)d_out;

    __half *Qh, *Kh, *Vh, *Shi, *Slo, *Xhi, *Xlo, *Wh;
    cudaGetSymbolAddress((void**)&Qh, g_Qh);
    cudaGetSymbolAddress((void**)&Kh, g_Kh);
    cudaGetSymbolAddress((void**)&Vh, g_Vh);
    cudaGetSymbolAddress((void**)&Shi, g_Shi);
    cudaGetSymbolAddress((void**)&Slo, g_Slo);
    cudaGetSymbolAddress((void**)&Xhi, g_Xhi);
    cudaGetSymbolAddress((void**)&Xlo, g_Xlo);
    cudaGetSymbolAddress((void**)&Wh, g_Wh);

    cudaFuncSetAttribute(gemm_mma<0>, cudaFuncAttributeMaxDynamicSharedMemorySize, GSMEM);
    cudaFuncSetAttribute(gemm_mma<1>, cudaFuncAttributeMaxDynamicSharedMemorySize, GSMEM);
    cudaFuncSetAttribute(attn_mma, cudaFuncAttributeMaxDynamicSharedMemorySize, ASMEM);

    const int xn4 = M_ * D_ / 4;
    split_kernel<<<(xn4 + 255) / 256, 256>>>((const float4*)X, (__half2*)Xhi, (__half2*)Xlo, xn4);
    const int wn4 = D_ * D_ / 4;
    for (int i = 0; i < 4; i++)
        cvt_kernel<<<(wn4 + 255) / 256, 256>>>((const float4*)W[i],
                                               (__half2*)(Wh + (size_t)i * D_ * D_), wn4);
    rope_tab_kernel<<<(L_ * 32 + 255) / 256, 256>>>();

    const dim3 gg(D_ / TN, M_ / TM);
    gemm_mma<1><<<gg, 256, GSMEM>>>(Xhi, Xlo, Wh + 0 * (size_t)D_ * D_, Qh);
    gemm_mma<1><<<gg, 256, GSMEM>>>(Xhi, Xlo, Wh + 1 * (size_t)D_ * D_, Kh);
    gemm_mma<1><<<gg, 256, GSMEM>>>(Xhi, Xlo, Wh + 2 * (size_t)D_ * D_, Vh);

    attn_mma<<<dim3(L_ / AQ, B_ * H_), 128, ASMEM>>>();

    gemm_mma<0><<<gg, 256, GSMEM>>>(Shi, Slo, Wh + 3 * (size_t)D_ * D_, out);
}

// round 6
// speedup vs baseline: 8.2424x; 1.6969x over previous
#include <cuda_runtime.h>
#include <cuda_fp16.h>
#include <math.h>
#include <stdint.h>

// Problem constants
constexpr int B_ = 4, L_ = 2048, D_ = 1024, H_ = 16, HD_ = 64;
constexpr int M_ = B_ * L_;
constexpr int WINDOW_ = 128;
constexpr size_t HSZ = (size_t)B_ * H_ * L_ * HD_;   // one head-tensor

// GEMM tiling
constexpr int TM = 128, TN = 128, KS = 32;
constexpr int NK = D_ / KS;
constexpr int ROWB = 80;                    // 32 halves = 64B -> 80B padded
constexpr int TILE_B = 128 * ROWB;          // 10240
constexpr int STAGE_B = 2 * TILE_B;         // A, W
constexpr int NSTG = 4;
constexpr int GSMEM = NSTG * STAGE_B;       // 81920

// Attention tiling
constexpr int AQ = 64;
constexpr int ANK = 192;
constexpr int ASTR = 144;
constexpr int OFF_Q = 0;
constexpr int OFF_K = OFF_Q + AQ * ASTR;
constexpr int OFF_V = OFF_K + ANK * ASTR;
constexpr int ASMEM = OFF_V + ANK * ASTR;   // 64512

// Scratch (device globals)
__device__ __half g_QKVh[3 * HSZ];          // Q | K | V in [B,H,L,hd]
__device__ __half g_Sh[(size_t)M_ * D_];    // attention out fp16 [B,L,D]
__device__ __half g_Xh[(size_t)M_ * D_];
__device__ __half g_Wh[4ull * D_ * D_];     // Wq Wk Wv Wo (fp16)
__device__ float g_cos[L_ * 32];
__device__ float g_sin[L_ * 32];

__device__ __forceinline__ uint32_t smem_u32(const void* p) {
    uint32_t a;
    asm("{ .reg .u64 t; cvta.to.shared.u64 t, %1; cvt.u32.u64 %0, t; }" : "=r"(a) : "l"(p));
    return a;
}

#define LDSM4(r, addr) \
    asm volatile("ldmatrix.sync.aligned.m8n8.x4.shared.b16 {%0,%1,%2,%3}, [%4];" \
                 : "=r"((r)[0]), "=r"((r)[1]), "=r"((r)[2]), "=r"((r)[3]) : "r"(addr))

#define LDSM4T(r, addr) \
    asm volatile("ldmatrix.sync.aligned.m8n8.x4.trans.shared.b16 {%0,%1,%2,%3}, [%4];" \
                 : "=r"((r)[0]), "=r"((r)[1]), "=r"((r)[2]), "=r"((r)[3]) : "r"(addr))

#define MMAH(d, a, b0, b1) \
    asm volatile("mma.sync.aligned.m16n8k16.row.col.f32.f16.f16.f32 " \
                 "{%0,%1,%2,%3}, {%4,%5,%6,%7}, {%8,%9}, {%0,%1,%2,%3};" \
                 : "+f"((d)[0]), "+f"((d)[1]), "+f"((d)[2]), "+f"((d)[3]) \
                 : "r"((a)[0]), "r"((a)[1]), "r"((a)[2]), "r"((a)[3]), "r"(b0), "r"(b1))

#define CP_WAIT(n) asm volatile("cp.async.wait_group %0;" :: "n"(n) : "memory")

__device__ __forceinline__ void cp16(uint32_t sa, const void* g) {
    asm volatile("cp.async.cg.shared.global [%0], [%1], 16;" :: "r"(sa), "l"(g));
}

__device__ __forceinline__ uint32_t pack_h2(float lo, float hi) {
    __half2 h = __floats2half2_rn(lo, hi);
    return *(uint32_t*)&h;
}

// Stage one K-chunk: A and W tiles, each 128 rows x 64B.
__device__ __forceinline__ void cp_stage(char* st, const __half* a, const __half* wt,
                                         int ko, int tid) {
    const __half* gp[2] = {a, wt};
    const uint32_t sb = smem_u32(st);
#pragma unroll
    for (int t = 0; t < 2; t++) {
#pragma unroll
        for (int rep = 0; rep < 2; rep++) {
            const int c = rep * 256 + tid;
            const int row = c >> 2, ch = c & 3;
            cp16(sb + t * TILE_B + row * ROWB + ch * 16,
                 gp[t] + (size_t)row * D_ + ko + ch * 8);
        }
    }
    asm volatile("cp.async.commit_group;" ::: "memory");
}

// ---------------------------------------------------------------------------
// Single-pass fp16 GEMM: C = A @ W^T.
// MODE 0: fp32 row-major out (final). MODE 1: fp16 head-scatter via gridDim.z.
// ---------------------------------------------------------------------------
template <int MODE>
__global__ void __launch_bounds__(256, 2) gemm_mma(const __half* __restrict__ A,
                                                   const __half* __restrict__ Wh,
                                                   void* __restrict__ outv) {
    extern __shared__ char sm[];
    const int tid = threadIdx.x;
    const int lane = tid & 31, wid = tid >> 5;
    const int mw = wid & 1, nw = wid >> 1;
    const int r0 = blockIdx.y * TM, n0 = blockIdx.x * TN;
    const int z = blockIdx.z;

    const __half* A_t = A + (size_t)r0 * D_;
    const __half* W_t = Wh + (size_t)z * D_ * D_ + (size_t)n0 * D_;

    float acc[4][4][4];
#pragma unroll
    for (int i = 0; i < 4; i++)
#pragma unroll
        for (int j = 0; j < 4; j++)
#pragma unroll
            for (int k = 0; k < 4; k++) acc[i][j][k] = 0.f;

    cp_stage(sm + 0 * STAGE_B, A_t, W_t, 0 * KS, tid);
    cp_stage(sm + 1 * STAGE_B, A_t, W_t, 1 * KS, tid);
    cp_stage(sm + 2 * STAGE_B, A_t, W_t, 2 * KS, tid);

    for (int kc = 0; kc < NK; kc++) {
        const int s = kc % NSTG;
        if (kc + 3 < NK) {
            cp_stage(sm + ((kc + 3) % NSTG) * STAGE_B, A_t, W_t, (kc + 3) * KS, tid);
            CP_WAIT(3);
        } else if (kc + 2 < NK) {
            CP_WAIT(2);
        } else if (kc + 1 < NK) {
            CP_WAIT(1);
        } else {
            CP_WAIT(0);
        }
        __syncthreads();

        const uint32_t sb = smem_u32(sm + s * STAGE_B);
        const uint32_t lrow = (lane & 15);
        const uint32_t lh = (lane >> 4) * 16;
#pragma unroll
        for (int kt = 0; kt < 2; kt++) {
            uint32_t bw[2][4];
#pragma unroll
            for (int np = 0; np < 2; np++)
                LDSM4(bw[np], sb + TILE_B + (nw * 32 + np * 16 + lrow) * ROWB + kt * 32 + lh);
#pragma unroll
            for (int mt = 0; mt < 4; mt++) {
                uint32_t ar[4];
                LDSM4(ar, sb + (mw * 64 + mt * 16 + lrow) * ROWB + kt * 32 + lh);
#pragma unroll
                for (int nt = 0; nt < 4; nt++)
                    MMAH(acc[mt][nt], ar, bw[nt >> 1][nt & 1], bw[nt >> 1][(nt & 1) + 2]);
            }
        }
        __syncthreads();
    }

#pragma unroll
    for (int mt = 0; mt < 4; mt++) {
#pragma unroll
        for (int nt = 0; nt < 4; nt++) {
            const int row = r0 + mw * 64 + mt * 16 + (lane >> 2);
            const int col = n0 + nw * 32 + nt * 8 + 2 * (lane & 3);
            if (MODE == 1) {
                __half* out = (__half*)outv + (size_t)z * HSZ;
                const int h = col >> 6, dd = col & 63;
                const int bb0 = row >> 11, l0 = row & (L_ - 1);
                const int r8 = row + 8;
                const int bb1 = r8 >> 11, l1 = r8 & (L_ - 1);
                *(__half2*)(out + (((size_t)bb0 * H_ + h) * L_ + l0) * HD_ + dd) =
                    __floats2half2_rn(acc[mt][nt][0], acc[mt][nt][1]);
                *(__half2*)(out + (((size_t)bb1 * H_ + h) * L_ + l1) * HD_ + dd) =
                    __floats2half2_rn(acc[mt][nt][2], acc[mt][nt][3]);
            } else {
                float* out = (float*)outv;
                *(float2*)(out + (size_t)row * D_ + col) =
                    make_float2(acc[mt][nt][0], acc[mt][nt][1]);
                *(float2*)(out + (size_t)(row + 8) * D_ + col) =
                    make_float2(acc[mt][nt][2], acc[mt][nt][3]);
            }
        }
    }
}

// fp32 -> fp16 round
__global__ void cvt_kernel(const float4* __restrict__ x, __half2* __restrict__ o, int n4) {
    const int i = blockIdx.x * blockDim.x + threadIdx.x;
    if (i >= n4) return;
    const float4 v = x[i];
    o[2 * i]     = __floats2half2_rn(v.x, v.y);
    o[2 * i + 1] = __floats2half2_rn(v.z, v.w);
}

// RoPE cos/sin table [L, 32]
__global__ void rope_tab_kernel() {
    const int i = blockIdx.x * blockDim.x + threadIdx.x;
    if (i >= L_ * 32) return;
    const int j = i & 31, l = i >> 5;
    const float invf = expf(-(float)j * 0.28782313662425575f);
    float s, c;
    sincosf((float)l * invf, &s, &c);
    g_cos[i] = c;
    g_sin[i] = s;
}

// ---------------------------------------------------------------------------
// Sliding-window attention: fp16 inputs, RoPE fused at load, mma.sync core.
// ---------------------------------------------------------------------------
__global__ void __launch_bounds__(128) attn_mma() {
    extern __shared__ char sm[];
    const uint32_t sb = smem_u32(sm);
    const int tid = threadIdx.x;
    const int lane = tid & 31, w = tid >> 5;
    const int bh = blockIdx.y;
    const int q0 = blockIdx.x * AQ;
    const int ks0 = q0 - (WINDOW_ - 1);
    const int jmin = (q0 < WINDOW_ - 1) ? (WINDOW_ - 1 - q0) : 0;

    // --- Q: load fp16, apply RoPE, store to smem ---
    const __half* Qg = g_QKVh + (size_t)bh * L_ * HD_ + (size_t)q0 * HD_;
    for (int idx = tid; idx < AQ * 8; idx += 128) {
        const int row = idx >> 3, d0 = (idx & 7) * 4;
        const __half* qp = Qg + (size_t)row * HD_ + d0;
        const uint2 ua = *(const uint2*)qp;
        const uint2 ub = *(const uint2*)(qp + 32);
        const __half2* ha = (const __half2*)&ua;
        const __half2* hb = (const __half2*)&ub;
        const float a[4] = {__low2float(ha[0]), __high2float(ha[0]),
                            __low2float(ha[1]), __high2float(ha[1])};
        const float b[4] = {__low2float(hb[0]), __high2float(hb[0]),
                            __low2float(hb[1]), __high2float(hb[1])};
        const float4 cc = *(const float4*)(g_cos + (q0 + row) * 32 + d0);
        const float4 ss = *(const float4*)(g_sin + (q0 + row) * 32 + d0);
        const float c[4] = {cc.x, cc.y, cc.z, cc.w};
        const float s[4] = {ss.x, ss.y, ss.z, ss.w};
        char* p = sm + OFF_Q + row * ASTR + d0 * 2;
#pragma unroll
        for (int e = 0; e < 4; e += 2) {
            *(__half2*)(p + e * 2) = __floats2half2_rn(a[e] * c[e] - b[e] * s[e],
                                                       a[e + 1] * c[e + 1] - b[e + 1] * s[e + 1]);
            *(__half2*)(p + 64 + e * 2) = __floats2half2_rn(b[e] * c[e] + a[e] * s[e],
                                                            b[e + 1] * c[e + 1] + a[e + 1] * s[e + 1]);
        }
    }
    // --- K: same with window offset, zero-fill OOB ---
    const __half* Kg = g_QKVh + HSZ + (size_t)bh * L_ * HD_;
    for (int idx = tid; idx < ANK * 8; idx += 128) {
        const int row = idx >> 3, d0 = (idx & 7) * 4;
        const int kg = ks0 + row;
        char* p = sm + OFF_K + row * ASTR + d0 * 2;
        if (kg < 0) {
            *(uint2*)p = make_uint2(0, 0);
            *(uint2*)(p + 64) = make_uint2(0, 0);
            continue;
        }
        const __half* kp = Kg + (size_t)kg * HD_ + d0;
        const uint2 ua = *(const uint2*)kp;
        const uint2 ub = *(const uint2*)(kp + 32);
        const __half2* ha = (const __half2*)&ua;
        const __half2* hb = (const __half2*)&ub;
        const float a[4] = {__low2float(ha[0]), __high2float(ha[0]),
                            __low2float(ha[1]), __high2float(ha[1])};
        const float b[4] = {__low2float(hb[0]), __high2float(hb[0]),
                            __low2float(hb[1]), __high2float(hb[1])};
        const float4 cc = *(const float4*)(g_cos + kg * 32 + d0);
        const float4 ss = *(const float4*)(g_sin + kg * 32 + d0);
        const float c[4] = {cc.x, cc.y, cc.z, cc.w};
        const float s[4] = {ss.x, ss.y, ss.z, ss.w};
#pragma unroll
        for (int e = 0; e < 4; e += 2) {
            *(__half2*)(p + e * 2) = __floats2half2_rn(a[e] * c[e] - b[e] * s[e],
                                                       a[e + 1] * c[e + 1] - b[e + 1] * s[e + 1]);
            *(__half2*)(p + 64 + e * 2) = __floats2half2_rn(b[e] * c[e] + a[e] * s[e],
                                                            b[e + 1] * c[e + 1] + a[e + 1] * s[e + 1]);
        }
    }
    // --- V: straight fp16 copy ---
    const __half* Vg = g_QKVh + 2 * HSZ + (size_t)bh * L_ * HD_;
    for (int idx = tid; idx < ANK * 8; idx += 128) {
        const int row = idx >> 3, c8 = idx & 7;
        const int kg = ks0 + row;
        uint4 v = make_uint4(0, 0, 0, 0);
        if (kg >= 0) v = *(const uint4*)(Vg + (size_t)kg * HD_ + c8 * 8);
        *(uint4*)(sm + OFF_V + row * ASTR + c8 * 16) = v;
    }
    __syncthreads();

    // --- S = Q K^T ---
    float sac[24][4];
#pragma unroll
    for (int f = 0; f < 24; f++)
#pragma unroll
        for (int k = 0; k < 4; k++) sac[f][k] = 0.f;

    const uint32_t lrow = (lane & 15);
    const uint32_t lh = (lane >> 4) * 16;
#pragma unroll
    for (int kt = 0; kt < 4; kt++) {
        uint32_t aq[4];
        LDSM4(aq, sb + OFF_Q + (16 * w + lrow) * ASTR + kt * 32 + lh);
#pragma unroll
        for (int nb = 0; nb < 12; nb++) {
            uint32_t bk[4];
            LDSM4(bk, sb + OFF_K + (nb * 16 + lrow) * ASTR + kt * 32 + lh);
            MMAH(sac[2 * nb],     aq, bk[0], bk[2]);
            MMAH(sac[2 * nb + 1], aq, bk[1], bk[3]);
        }
    }

    // --- mask + softmax (register-resident) ---
    const int i1 = 16 * w + (lane >> 2);
    const int i2 = i1 + 8;
    const int cq = (lane & 3) * 2;
    constexpr float SCALE = 0.125f;
    float m1 = -1e30f, m2 = -1e30f;
#pragma unroll
    for (int f = 0; f < 24; f++) {
        const int j0 = 8 * f + cq, j1 = j0 + 1;
        const bool k00 = ((unsigned)(j0 - i1) < (unsigned)WINDOW_) && j0 >= jmin;
        const bool k01 = ((unsigned)(j1 - i1) < (unsigned)WINDOW_) && j1 >= jmin;
        const bool k10 = ((unsigned)(j0 - i2) < (unsigned)WINDOW_) && j0 >= jmin;
        const bool k11 = ((unsigned)(j1 - i2) < (unsigned)WINDOW_) && j1 >= jmin;
        sac[f][0] = k00 ? sac[f][0] * SCALE : -1e30f;
        sac[f][1] = k01 ? sac[f][1] * SCALE : -1e30f;
        sac[f][2] = k10 ? sac[f][2] * SCALE : -1e30f;
        sac[f][3] = k11 ? sac[f][3] * SCALE : -1e30f;
        m1 = fmaxf(m1, fmaxf(sac[f][0], sac[f][1]));
        m2 = fmaxf(m2, fmaxf(sac[f][2], sac[f][3]));
    }
    m1 = fmaxf(m1, __shfl_xor_sync(0xffffffffu, m1, 1));
    m1 = fmaxf(m1, __shfl_xor_sync(0xffffffffu, m1, 2));
    m2 = fmaxf(m2, __shfl_xor_sync(0xffffffffu, m2, 1));
    m2 = fmaxf(m2, __shfl_xor_sync(0xffffffffu, m2, 2));

    float l1 = 0.f, l2 = 0.f;
#pragma unroll
    for (int f = 0; f < 24; f++) {
        sac[f][0] = __expf(sac[f][0] - m1);
        sac[f][1] = __expf(sac[f][1] - m1);
        sac[f][2] = __expf(sac[f][2] - m2);
        sac[f][3] = __expf(sac[f][3] - m2);
        l1 += sac[f][0] + sac[f][1];
        l2 += sac[f][2] + sac[f][3];
    }
    l1 += __shfl_xor_sync(0xffffffffu, l1, 1);
    l1 += __shfl_xor_sync(0xffffffffu, l1, 2);
    l2 += __shfl_xor_sync(0xffffffffu, l2, 1);
    l2 += __shfl_xor_sync(0xffffffffu, l2, 2);

    // --- O = P V (V via ldmatrix.trans) ---
    float oac[8][4];
#pragma unroll
    for (int f = 0; f < 8; f++)
#pragma unroll
        for (int k = 0; k < 4; k++) oac[f][k] = 0.f;

#pragma unroll
    for (int kb = 0; kb < 12; kb++) {
        uint32_t pa[4];
        pa[0] = pack_h2(sac[2 * kb][0],     sac[2 * kb][1]);
        pa[1] = pack_h2(sac[2 * kb][2],     sac[2 * kb][3]);
        pa[2] = pack_h2(sac[2 * kb + 1][0], sac[2 * kb + 1][1]);
        pa[3] = pack_h2(sac[2 * kb + 1][2], sac[2 * kb + 1][3]);
#pragma unroll
        for (int db = 0; db < 4; db++) {
            uint32_t bv[4];
            LDSM4T(bv, sb + OFF_V + (kb * 16 + lrow) * ASTR + db * 32 + lh);
            MMAH(oac[2 * db],     pa, bv[0], bv[1]);
            MMAH(oac[2 * db + 1], pa, bv[2], bv[3]);
        }
    }

    // --- epilogue: normalize, write fp16 S [B,L,D] ---
    const float inv1 = 1.f / l1, inv2 = 1.f / l2;
    const int bb = bh >> 4, h = bh & (H_ - 1);
    const size_t off1 = ((size_t)bb * L_ + q0 + i1) * D_ + h * HD_;
    const size_t off2 = ((size_t)bb * L_ + q0 + i2) * D_ + h * HD_;
#pragma unroll
    for (int f = 0; f < 8; f++) {
        const int d0 = 8 * f + cq;
        *(__half2*)(g_Sh + off1 + d0) =
            __floats2half2_rn(oac[f][0] * inv1, oac[f][1] * inv1);
        *(__half2*)(g_Sh + off2 + d0) =
            __floats2half2_rn(oac[f][2] * inv2, oac[f][3] * inv2);
    }
}

// ---------------------------------------------------------------------------
extern "C" void kernel_launch(void* const* d_in, const int* in_sizes, int n_in,
                              void* d_out, int out_size) {
    const float* X = (const float*)d_in[0];
    const float* W[4] = {(const float*)d_in[1], (const float*)d_in[2],
                         (const float*)d_in[3], (const float*)d_in[4]};
    float* out = (float*)d_out;

    __half *QKVh, *Sh, *Xh, *Wh;
    cudaGetSymbolAddress((void**)&QKVh, g_QKVh);
    cudaGetSymbolAddress((void**)&Sh, g_Sh);
    cudaGetSymbolAddress((void**)&Xh, g_Xh);
    cudaGetSymbolAddress((void**)&Wh, g_Wh);

    cudaFuncSetAttribute(gemm_mma<0>, cudaFuncAttributeMaxDynamicSharedMemorySize, GSMEM);
    cudaFuncSetAttribute(gemm_mma<1>, cudaFuncAttributeMaxDynamicSharedMemorySize, GSMEM);
    cudaFuncSetAttribute(attn_mma, cudaFuncAttributeMaxDynamicSharedMemorySize, ASMEM);

    const int xn4 = M_ * D_ / 4;
    cvt_kernel<<<(xn4 + 255) / 256, 256>>>((const float4*)X, (__half2*)Xh, xn4);
    const int wn4 = D_ * D_ / 4;
    for (int i = 0; i < 4; i++)
        cvt_kernel<<<(wn4 + 255) / 256, 256>>>((const float4*)W[i],
                                               (__half2*)(Wh + (size_t)i * D_ * D_), wn4);
    rope_tab_kernel<<<(L_ * 32 + 255) / 256, 256>>>();

    // Fused QKV: gridDim.z selects the weight matrix & output slice
    gemm_mma<1><<<dim3(D_ / TN, M_ / TM, 3), 256, GSMEM>>>(Xh, Wh, QKVh);

    attn_mma<<<dim3(L_ / AQ, B_ * H_), 128, ASMEM>>>();

    // O projection (z=0 with Wo pointer)
    gemm_mma<0><<<dim3(D_ / TN, M_ / TM, 1), 256, GSMEM>>>(Sh, Wh + 3 * (size_t)D_ * D_, out);
}

// round 7
// speedup vs baseline: 8.4097x; 1.0203x over previous
#include <cuda_runtime.h>
#include <cuda_fp16.h>
#include <math.h>
#include <stdint.h>

// Problem constants
constexpr int B_ = 4, L_ = 2048, D_ = 1024, H_ = 16, HD_ = 64;
constexpr int M_ = B_ * L_;
constexpr int WINDOW_ = 128;
constexpr size_t HSZ = (size_t)B_ * H_ * L_ * HD_;

// GEMM tiling
constexpr int TM = 128, TN = 128, KS = 32;
constexpr int NK = D_ / KS;
constexpr int ROWB = 80;
constexpr int TILE_B = 128 * ROWB;
constexpr int STAGE_B = 2 * TILE_B;
constexpr int NSTG = 4;
constexpr int GSMEM = NSTG * STAGE_B;       // 81920

// Attention tiling (key-split across warp halves)
constexpr int AQ = 64;
constexpr int ANK = 192;
constexpr int ASTR = 144;
constexpr int OFF_Q = 0;
constexpr int OFF_K = OFF_Q + AQ * ASTR;     // 9216
constexpr int OFF_V = OFF_K + ANK * ASTR;    // 36864
constexpr int OFF_O1 = OFF_V + ANK * ASTR;   // 64512 (64 x 66 fp32)
constexpr int OFF_M1 = OFF_O1 + 64 * 66 * 4; // 81408
constexpr int OFF_L1 = OFF_M1 + 64 * 4;      // 81664
constexpr int ASMEM = OFF_L1 + 64 * 4;       // 81920

// Scratch (device globals)
__device__ __half g_QKVh[3 * HSZ];
__device__ __half g_Sh[(size_t)M_ * D_];
__device__ __half g_Xh[(size_t)M_ * D_];
__device__ __half g_Wh[4ull * D_ * D_];
__device__ float g_cos[L_ * 32];
__device__ float g_sin[L_ * 32];

__device__ __forceinline__ uint32_t smem_u32(const void* p) {
    uint32_t a;
    asm("{ .reg .u64 t; cvta.to.shared.u64 t, %1; cvt.u32.u64 %0, t; }" : "=r"(a) : "l"(p));
    return a;
}

#define LDSM4(r, addr) \
    asm volatile("ldmatrix.sync.aligned.m8n8.x4.shared.b16 {%0,%1,%2,%3}, [%4];" \
                 : "=r"((r)[0]), "=r"((r)[1]), "=r"((r)[2]), "=r"((r)[3]) : "r"(addr))

#define LDSM4T(r, addr) \
    asm volatile("ldmatrix.sync.aligned.m8n8.x4.trans.shared.b16 {%0,%1,%2,%3}, [%4];" \
                 : "=r"((r)[0]), "=r"((r)[1]), "=r"((r)[2]), "=r"((r)[3]) : "r"(addr))

#define MMAH(d, a, b0, b1) \
    asm volatile("mma.sync.aligned.m16n8k16.row.col.f32.f16.f16.f32 " \
                 "{%0,%1,%2,%3}, {%4,%5,%6,%7}, {%8,%9}, {%0,%1,%2,%3};" \
                 : "+f"((d)[0]), "+f"((d)[1]), "+f"((d)[2]), "+f"((d)[3]) \
                 : "r"((a)[0]), "r"((a)[1]), "r"((a)[2]), "r"((a)[3]), "r"(b0), "r"(b1))

#define CP_WAIT(n) asm volatile("cp.async.wait_group %0;" :: "n"(n) : "memory")

__device__ __forceinline__ void cp16(uint32_t sa, const void* g) {
    asm volatile("cp.async.cg.shared.global [%0], [%1], 16;" :: "r"(sa), "l"(g));
}

__device__ __forceinline__ uint32_t pack_h2(float lo, float hi) {
    __half2 h = __floats2half2_rn(lo, hi);
    return *(uint32_t*)&h;
}

__device__ __forceinline__ void cp_stage(char* st, const __half* a, const __half* wt,
                                         int ko, int tid) {
    const __half* gp[2] = {a, wt};
    const uint32_t sb = smem_u32(st);
#pragma unroll
    for (int t = 0; t < 2; t++) {
#pragma unroll
        for (int rep = 0; rep < 2; rep++) {
            const int c = rep * 256 + tid;
            const int row = c >> 2, ch = c & 3;
            cp16(sb + t * TILE_B + row * ROWB + ch * 16,
                 gp[t] + (size_t)row * D_ + ko + ch * 8);
        }
    }
    asm volatile("cp.async.commit_group;" ::: "memory");
}

// ---------------------------------------------------------------------------
// Single-pass fp16 GEMM: C = A @ W^T.
// MODE 0: fp32 row-major. MODE 1: fp16 head-scatter via gridDim.z.
// ---------------------------------------------------------------------------
template <int MODE>
__global__ void __launch_bounds__(256, 2) gemm_mma(const __half* __restrict__ A,
                                                   const __half* __restrict__ Wh,
                                                   void* __restrict__ outv) {
    extern __shared__ char sm[];
    const int tid = threadIdx.x;
    const int lane = tid & 31, wid = tid >> 5;
    const int mw = wid & 1, nw = wid >> 1;
    const int r0 = blockIdx.y * TM, n0 = blockIdx.x * TN;
    const int z = blockIdx.z;

    const __half* A_t = A + (size_t)r0 * D_;
    const __half* W_t = Wh + (size_t)z * D_ * D_ + (size_t)n0 * D_;

    float acc[4][4][4];
#pragma unroll
    for (int i = 0; i < 4; i++)
#pragma unroll
        for (int j = 0; j < 4; j++)
#pragma unroll
            for (int k = 0; k < 4; k++) acc[i][j][k] = 0.f;

    cp_stage(sm + 0 * STAGE_B, A_t, W_t, 0 * KS, tid);
    cp_stage(sm + 1 * STAGE_B, A_t, W_t, 1 * KS, tid);
    cp_stage(sm + 2 * STAGE_B, A_t, W_t, 2 * KS, tid);

    for (int kc = 0; kc < NK; kc++) {
        const int s = kc % NSTG;
        if (kc + 3 < NK) {
            cp_stage(sm + ((kc + 3) % NSTG) * STAGE_B, A_t, W_t, (kc + 3) * KS, tid);
            CP_WAIT(3);
        } else if (kc + 2 < NK) {
            CP_WAIT(2);
        } else if (kc + 1 < NK) {
            CP_WAIT(1);
        } else {
            CP_WAIT(0);
        }
        __syncthreads();

        const uint32_t sb = smem_u32(sm + s * STAGE_B);
        const uint32_t lrow = (lane & 15);
        const uint32_t lh = (lane >> 4) * 16;
#pragma unroll
        for (int kt = 0; kt < 2; kt++) {
            uint32_t bw[2][4];
#pragma unroll
            for (int np = 0; np < 2; np++)
                LDSM4(bw[np], sb + TILE_B + (nw * 32 + np * 16 + lrow) * ROWB + kt * 32 + lh);
#pragma unroll
            for (int mt = 0; mt < 4; mt++) {
                uint32_t ar[4];
                LDSM4(ar, sb + (mw * 64 + mt * 16 + lrow) * ROWB + kt * 32 + lh);
#pragma unroll
                for (int nt = 0; nt < 4; nt++)
                    MMAH(acc[mt][nt], ar, bw[nt >> 1][nt & 1], bw[nt >> 1][(nt & 1) + 2]);
            }
        }
        __syncthreads();
    }

#pragma unroll
    for (int mt = 0; mt < 4; mt++) {
#pragma unroll
        for (int nt = 0; nt < 4; nt++) {
            const int row = r0 + mw * 64 + mt * 16 + (lane >> 2);
            const int col = n0 + nw * 32 + nt * 8 + 2 * (lane & 3);
            if (MODE == 1) {
                __half* out = (__half*)outv + (size_t)z * HSZ;
                const int h = col >> 6, dd = col & 63;
                const int bb0 = row >> 11, l0 = row & (L_ - 1);
                const int r8 = row + 8;
                const int bb1 = r8 >> 11, l1 = r8 & (L_ - 1);
                *(__half2*)(out + (((size_t)bb0 * H_ + h) * L_ + l0) * HD_ + dd) =
                    __floats2half2_rn(acc[mt][nt][0], acc[mt][nt][1]);
                *(__half2*)(out + (((size_t)bb1 * H_ + h) * L_ + l1) * HD_ + dd) =
                    __floats2half2_rn(acc[mt][nt][2], acc[mt][nt][3]);
            } else {
                float* out = (float*)outv;
                *(float2*)(out + (size_t)row * D_ + col) =
                    make_float2(acc[mt][nt][0], acc[mt][nt][1]);
                *(float2*)(out + (size_t)(row + 8) * D_ + col) =
                    make_float2(acc[mt][nt][2], acc[mt][nt][3]);
            }
        }
    }
}

// ---------------------------------------------------------------------------
// Fused prep: X->fp16, W0..W3->fp16, RoPE cos/sin table. One launch.
// ---------------------------------------------------------------------------
constexpr int XN4 = M_ * D_ / 4;      // 2^21
constexpr int WN4 = D_ * D_ / 4;      // 2^18
constexpr int PREP_N = XN4 + 4 * WN4 + L_ * 32;

__global__ void prep_kernel(const float4* __restrict__ X,
                            const float4* __restrict__ W0, const float4* __restrict__ W1,
                            const float4* __restrict__ W2, const float4* __restrict__ W3) {
    const int i = blockIdx.x * blockDim.x + threadIdx.x;
    if (i < XN4) {
        const float4 v = X[i];
        __half2* o = (__half2*)g_Xh;
        o[2 * i]     = __floats2half2_rn(v.x, v.y);
        o[2 * i + 1] = __floats2half2_rn(v.z, v.w);
    } else if (i < XN4 + 4 * WN4) {
        const int widx = i - XN4;
        const int wi = widx >> 18, off = widx & (WN4 - 1);
        const float4* Wp = (wi == 0) ? W0 : (wi == 1) ? W1 : (wi == 2) ? W2 : W3;
        const float4 v = Wp[off];
        __half2* o = (__half2*)(g_Wh + (size_t)wi * D_ * D_);
        o[2 * off]     = __floats2half2_rn(v.x, v.y);
        o[2 * off + 1] = __floats2half2_rn(v.z, v.w);
    } else {
        const int r = i - XN4 - 4 * WN4;
        if (r < L_ * 32) {
            const int j = r & 31, l = r >> 5;
            const float invf = expf(-(float)j * 0.28782313662425575f);
            float s, c;
            sincosf((float)l * invf, &s, &c);
            g_cos[r] = c;
            g_sin[r] = s;
        }
    }
}

// ---------------------------------------------------------------------------
// Sliding-window attention, key-split: 256 threads, warps 0-3 keys [0,96),
// warps 4-7 keys [96,192); flash-merge of (m,l,O) partials via smem.
// ---------------------------------------------------------------------------
__global__ void __launch_bounds__(256, 2) attn_mma() {
    extern __shared__ char sm[];
    const uint32_t sb = smem_u32(sm);
    const int tid = threadIdx.x;
    const int lane = tid & 31, w = tid >> 5;
    const int half = w >> 2, wq = w & 3;
    const int kbase = half * 96;
    const int bh = blockIdx.y;
    const int q0 = blockIdx.x * AQ;
    const int ks0 = q0 - (WINDOW_ - 1);
    const int jmin = (q0 < WINDOW_ - 1) ? (WINDOW_ - 1 - q0) : 0;

    // --- Q: load fp16, apply RoPE ---
    const __half* Qg = g_QKVh + (size_t)bh * L_ * HD_ + (size_t)q0 * HD_;
    for (int idx = tid; idx < AQ * 8; idx += 256) {
        const int row = idx >> 3, d0 = (idx & 7) * 4;
        const __half* qp = Qg + (size_t)row * HD_ + d0;
        const uint2 ua = *(const uint2*)qp;
        const uint2 ub = *(const uint2*)(qp + 32);
        const __half2* ha = (const __half2*)&ua;
        const __half2* hb = (const __half2*)&ub;
        const float a[4] = {__low2float(ha[0]), __high2float(ha[0]),
                            __low2float(ha[1]), __high2float(ha[1])};
        const float b[4] = {__low2float(hb[0]), __high2float(hb[0]),
                            __low2float(hb[1]), __high2float(hb[1])};
        const float4 cc = *(const float4*)(g_cos + (q0 + row) * 32 + d0);
        const float4 ss = *(const float4*)(g_sin + (q0 + row) * 32 + d0);
        const float c[4] = {cc.x, cc.y, cc.z, cc.w};
        const float s[4] = {ss.x, ss.y, ss.z, ss.w};
        char* p = sm + OFF_Q + row * ASTR + d0 * 2;
#pragma unroll
        for (int e = 0; e < 4; e += 2) {
            *(__half2*)(p + e * 2) = __floats2half2_rn(a[e] * c[e] - b[e] * s[e],
                                                       a[e + 1] * c[e + 1] - b[e + 1] * s[e + 1]);
            *(__half2*)(p + 64 + e * 2) = __floats2half2_rn(b[e] * c[e] + a[e] * s[e],
                                                            b[e + 1] * c[e + 1] + a[e + 1] * s[e + 1]);
        }
    }
    // --- K: RoPE + window offset, zero-fill OOB ---
    const __half* Kg = g_QKVh + HSZ + (size_t)bh * L_ * HD_;
    for (int idx = tid; idx < ANK * 8; idx += 256) {
        const int row = idx >> 3, d0 = (idx & 7) * 4;
        const int kg = ks0 + row;
        char* p = sm + OFF_K + row * ASTR + d0 * 2;
        if (kg < 0) {
            *(uint2*)p = make_uint2(0, 0);
            *(uint2*)(p + 64) = make_uint2(0, 0);
            continue;
        }
        const __half* kp = Kg + (size_t)kg * HD_ + d0;
        const uint2 ua = *(const uint2*)kp;
        const uint2 ub = *(const uint2*)(kp + 32);
        const __half2* ha = (const __half2*)&ua;
        const __half2* hb = (const __half2*)&ub;
        const float a[4] = {__low2float(ha[0]), __high2float(ha[0]),
                            __low2float(ha[1]), __high2float(ha[1])};
        const float b[4] = {__low2float(hb[0]), __high2float(hb[0]),
                            __low2float(hb[1]), __high2float(hb[1])};
        const float4 cc = *(const float4*)(g_cos + kg * 32 + d0);
        const float4 ss = *(const float4*)(g_sin + kg * 32 + d0);
        const float c[4] = {cc.x, cc.y, cc.z, cc.w};
        const float s[4] = {ss.x, ss.y, ss.z, ss.w};
#pragma unroll
        for (int e = 0; e < 4; e += 2) {
            *(__half2*)(p + e * 2) = __floats2half2_rn(a[e] * c[e] - b[e] * s[e],
                                                       a[e + 1] * c[e + 1] - b[e + 1] * s[e + 1]);
            *(__half2*)(p + 64 + e * 2) = __floats2half2_rn(b[e] * c[e] + a[e] * s[e],
                                                            b[e + 1] * c[e + 1] + a[e + 1] * s[e + 1]);
        }
    }
    // --- V copy ---
    const __half* Vg = g_QKVh + 2 * HSZ + (size_t)bh * L_ * HD_;
    for (int idx = tid; idx < ANK * 8; idx += 256) {
        const int row = idx >> 3, c8 = idx & 7;
        const int kg = ks0 + row;
        uint4 v = make_uint4(0, 0, 0, 0);
        if (kg >= 0) v = *(const uint4*)(Vg + (size_t)kg * HD_ + c8 * 8);
        *(uint4*)(sm + OFF_V + row * ASTR + c8 * 16) = v;
    }
    __syncthreads();

    // --- S = Q K^T over this warp's 96-key half ---
    float sac[12][4];
#pragma unroll
    for (int f = 0; f < 12; f++)
#pragma unroll
        for (int k = 0; k < 4; k++) sac[f][k] = 0.f;

    const uint32_t lrow = (lane & 15);
    const uint32_t lh = (lane >> 4) * 16;
#pragma unroll
    for (int kt = 0; kt < 4; kt++) {
        uint32_t aq[4];
        LDSM4(aq, sb + OFF_Q + (16 * wq + lrow) * ASTR + kt * 32 + lh);
#pragma unroll
        for (int nb = 0; nb < 6; nb++) {
            uint32_t bk[4];
            LDSM4(bk, sb + OFF_K + (kbase + nb * 16 + lrow) * ASTR + kt * 32 + lh);
            MMAH(sac[2 * nb],     aq, bk[0], bk[2]);
            MMAH(sac[2 * nb + 1], aq, bk[1], bk[3]);
        }
    }

    // --- mask + partial softmax ---
    const int i1 = 16 * wq + (lane >> 2);
    const int i2 = i1 + 8;
    const int cq = (lane & 3) * 2;
    constexpr float SCALE = 0.125f;
    float m1 = -1e30f, m2 = -1e30f;
#pragma unroll
    for (int f = 0; f < 12; f++) {
        const int j0 = kbase + 8 * f + cq, j1 = j0 + 1;
        const bool k00 = ((unsigned)(j0 - i1) < (unsigned)WINDOW_) && j0 >= jmin;
        const bool k01 = ((unsigned)(j1 - i1) < (unsigned)WINDOW_) && j1 >= jmin;
        const bool k10 = ((unsigned)(j0 - i2) < (unsigned)WINDOW_) && j0 >= jmin;
        const bool k11 = ((unsigned)(j1 - i2) < (unsigned)WINDOW_) && j1 >= jmin;
        sac[f][0] = k00 ? sac[f][0] * SCALE : -1e30f;
        sac[f][1] = k01 ? sac[f][1] * SCALE : -1e30f;
        sac[f][2] = k10 ? sac[f][2] * SCALE : -1e30f;
        sac[f][3] = k11 ? sac[f][3] * SCALE : -1e30f;
        m1 = fmaxf(m1, fmaxf(sac[f][0], sac[f][1]));
        m2 = fmaxf(m2, fmaxf(sac[f][2], sac[f][3]));
    }
    m1 = fmaxf(m1, __shfl_xor_sync(0xffffffffu, m1, 1));
    m1 = fmaxf(m1, __shfl_xor_sync(0xffffffffu, m1, 2));
    m2 = fmaxf(m2, __shfl_xor_sync(0xffffffffu, m2, 1));
    m2 = fmaxf(m2, __shfl_xor_sync(0xffffffffu, m2, 2));

    float l1 = 0.f, l2 = 0.f;
#pragma unroll
    for (int f = 0; f < 12; f++) {
        sac[f][0] = __expf(sac[f][0] - m1);
        sac[f][1] = __expf(sac[f][1] - m1);
        sac[f][2] = __expf(sac[f][2] - m2);
        sac[f][3] = __expf(sac[f][3] - m2);
        l1 += sac[f][0] + sac[f][1];
        l2 += sac[f][2] + sac[f][3];
    }
    l1 += __shfl_xor_sync(0xffffffffu, l1, 1);
    l1 += __shfl_xor_sync(0xffffffffu, l1, 2);
    l2 += __shfl_xor_sync(0xffffffffu, l2, 1);
    l2 += __shfl_xor_sync(0xffffffffu, l2, 2);

    // --- O_partial = P V over this half's keys ---
    float oac[8][4];
#pragma unroll
    for (int f = 0; f < 8; f++)
#pragma unroll
        for (int k = 0; k < 4; k++) oac[f][k] = 0.f;

#pragma unroll
    for (int kb = 0; kb < 6; kb++) {
        uint32_t pa[4];
        pa[0] = pack_h2(sac[2 * kb][0],     sac[2 * kb][1]);
        pa[1] = pack_h2(sac[2 * kb][2],     sac[2 * kb][3]);
        pa[2] = pack_h2(sac[2 * kb + 1][0], sac[2 * kb + 1][1]);
        pa[3] = pack_h2(sac[2 * kb + 1][2], sac[2 * kb + 1][3]);
#pragma unroll
        for (int db = 0; db < 4; db++) {
            uint32_t bv[4];
            LDSM4T(bv, sb + OFF_V + (kbase + kb * 16 + lrow) * ASTR + db * 32 + lh);
            MMAH(oac[2 * db],     pa, bv[0], bv[1]);
            MMAH(oac[2 * db + 1], pa, bv[2], bv[3]);
        }
    }

    // --- merge halves via smem ---
    float* O1 = (float*)(sm + OFF_O1);
    float* sm_m = (float*)(sm + OFF_M1);
    float* sm_l = (float*)(sm + OFF_L1);

    if (half == 0) {
#pragma unroll
        for (int f = 0; f < 8; f++) {
            const int d0 = 8 * f + cq;
            O1[i1 * 66 + d0]     = oac[f][0];
            O1[i1 * 66 + d0 + 1] = oac[f][1];
            O1[i2 * 66 + d0]     = oac[f][2];
            O1[i2 * 66 + d0 + 1] = oac[f][3];
        }
        if ((lane & 3) == 0) {
            sm_m[i1] = m1; sm_l[i1] = l1;
            sm_m[i2] = m2; sm_l[i2] = l2;
        }
    }
    __syncthreads();

    if (half == 1) {
        const float m1s = sm_m[i1], l1s = sm_l[i1];
        const float m2s = sm_m[i2], l2s = sm_l[i2];
        const float M1 = fmaxf(m1s, m1), M2 = fmaxf(m2s, m2);
        const float a1 = __expf(m1s - M1), b1 = __expf(m1 - M1);
        const float a2 = __expf(m2s - M2), b2 = __expf(m2 - M2);
        const float inv1 = 1.f / (a1 * l1s + b1 * l1);
        const float inv2 = 1.f / (a2 * l2s + b2 * l2);

        const int bb = bh >> 4, h = bh & (H_ - 1);
        const size_t off1 = ((size_t)bb * L_ + q0 + i1) * D_ + h * HD_;
        const size_t off2 = ((size_t)bb * L_ + q0 + i2) * D_ + h * HD_;
#pragma unroll
        for (int f = 0; f < 8; f++) {
            const int d0 = 8 * f + cq;
            const float v10 = (a1 * O1[i1 * 66 + d0]     + b1 * oac[f][0]) * inv1;
            const float v11 = (a1 * O1[i1 * 66 + d0 + 1] + b1 * oac[f][1]) * inv1;
            const float v20 = (a2 * O1[i2 * 66 + d0]     + b2 * oac[f][2]) * inv2;
            const float v21 = (a2 * O1[i2 * 66 + d0 + 1] + b2 * oac[f][3]) * inv2;
            *(__half2*)(g_Sh + off1 + d0) = __floats2half2_rn(v10, v11);
            *(__half2*)(g_Sh + off2 + d0) = __floats2half2_rn(v20, v21);
        }
    }
}

// ---------------------------------------------------------------------------
extern "C" void kernel_launch(void* const* d_in, const int* in_sizes, int n_in,
                              void* d_out, int out_size) {
    const float* X = (const float*)d_in[0];
    float* out = (float*)d_out;

    __half *QKVh, *Sh, *Xh, *Wh;
    cudaGetSymbolAddress((void**)&QKVh, g_QKVh);
    cudaGetSymbolAddress((void**)&Sh, g_Sh);
    cudaGetSymbolAddress((void**)&Xh, g_Xh);
    cudaGetSymbolAddress((void**)&Wh, g_Wh);

    cudaFuncSetAttribute(gemm_mma<0>, cudaFuncAttributeMaxDynamicSharedMemorySize, GSMEM);
    cudaFuncSetAttribute(gemm_mma<1>, cudaFuncAttributeMaxDynamicSharedMemorySize, GSMEM);
    cudaFuncSetAttribute(attn_mma, cudaFuncAttributeMaxDynamicSharedMemorySize, ASMEM);

    prep_kernel<<<(PREP_N + 255) / 256, 256>>>((const float4*)X,
                                               (const float4*)d_in[1], (const float4*)d_in[2],
                                               (const float4*)d_in[3], (const float4*)d_in[4]);

    gemm_mma<1><<<dim3(D_ / TN, M_ / TM, 3), 256, GSMEM>>>(Xh, Wh, QKVh);

    attn_mma<<<dim3(L_ / AQ, B_ * H_), 256, ASMEM>>>();

    gemm_mma<0><<<dim3(D_ / TN, M_ / TM, 1), 256, GSMEM>>>(Sh, Wh + 3 * (size_t)D_ * D_, out);
}

// round 8
// speedup vs baseline: 9.4901x; 1.1285x over previous
#include <cuda_runtime.h>
#include <cuda_fp16.h>
#include <math.h>
#include <stdint.h>

// Problem constants
constexpr int B_ = 4, L_ = 2048, D_ = 1024, H_ = 16, HD_ = 64;
constexpr int M_ = B_ * L_;
constexpr int WINDOW_ = 128;
constexpr size_t HSZ = (size_t)B_ * H_ * L_ * HD_;

// GEMM tiling: CTA 128x128, K-step 64, 3-stage pipeline, 1 sync/iter.
constexpr int TM = 128, TN = 128, KS = 64;
constexpr int NK2 = D_ / KS;                // 16 iterations
constexpr int ROWB = 144;                   // 64 halves = 128B -> 144B padded
constexpr int TILE_B = 128 * ROWB;          // 18432
constexpr int STAGE_B = 2 * TILE_B;         // A, W = 36864
constexpr int NSTG = 3;
constexpr int GSMEM = NSTG * STAGE_B;       // 110592

// Attention tiling (key-split across warp halves)
constexpr int AQ = 64;
constexpr int ANK = 192;
constexpr int ASTR = 144;
constexpr int OFF_Q = 0;
constexpr int OFF_K = OFF_Q + AQ * ASTR;
constexpr int OFF_V = OFF_K + ANK * ASTR;
constexpr int OFF_O1 = OFF_V + ANK * ASTR;
constexpr int OFF_M1 = OFF_O1 + 64 * 66 * 4;
constexpr int OFF_L1 = OFF_M1 + 64 * 4;
constexpr int ASMEM = OFF_L1 + 64 * 4;      // 81920

// Scratch (device globals)
__device__ __half g_QKVh[3 * HSZ];
__device__ __half g_Sh[(size_t)M_ * D_];
__device__ __half g_Xh[(size_t)M_ * D_];
__device__ __half g_Wh[4ull * D_ * D_];
__device__ float g_cos[L_ * 32];
__device__ float g_sin[L_ * 32];

__device__ __forceinline__ uint32_t smem_u32(const void* p) {
    uint32_t a;
    asm("{ .reg .u64 t; cvta.to.shared.u64 t, %1; cvt.u32.u64 %0, t; }" : "=r"(a) : "l"(p));
    return a;
}

#define LDSM4(r, addr) \
    asm volatile("ldmatrix.sync.aligned.m8n8.x4.shared.b16 {%0,%1,%2,%3}, [%4];" \
                 : "=r"((r)[0]), "=r"((r)[1]), "=r"((r)[2]), "=r"((r)[3]) : "r"(addr))

#define LDSM4T(r, addr) \
    asm volatile("ldmatrix.sync.aligned.m8n8.x4.trans.shared.b16 {%0,%1,%2,%3}, [%4];" \
                 : "=r"((r)[0]), "=r"((r)[1]), "=r"((r)[2]), "=r"((r)[3]) : "r"(addr))

#define MMAH(d, a, b0, b1) \
    asm volatile("mma.sync.aligned.m16n8k16.row.col.f32.f16.f16.f32 " \
                 "{%0,%1,%2,%3}, {%4,%5,%6,%7}, {%8,%9}, {%0,%1,%2,%3};" \
                 : "+f"((d)[0]), "+f"((d)[1]), "+f"((d)[2]), "+f"((d)[3]) \
                 : "r"((a)[0]), "r"((a)[1]), "r"((a)[2]), "r"((a)[3]), "r"(b0), "r"(b1))

#define CP_WAIT(n) asm volatile("cp.async.wait_group %0;" :: "n"(n) : "memory")

__device__ __forceinline__ void cp16(uint32_t sa, const void* g) {
    asm volatile("cp.async.cg.shared.global [%0], [%1], 16;" :: "r"(sa), "l"(g));
}

__device__ __forceinline__ uint32_t pack_h2(float lo, float hi) {
    __half2 h = __floats2half2_rn(lo, hi);
    return *(uint32_t*)&h;
}

// Stage one 64-wide K-chunk: A and W tiles, each 128 rows x 128B (8 cp16/row).
__device__ __forceinline__ void cp_stage(char* st, const __half* a, const __half* wt,
                                         int ko, int tid) {
    const __half* gp[2] = {a, wt};
    const uint32_t sb = smem_u32(st);
#pragma unroll
    for (int t = 0; t < 2; t++) {
#pragma unroll
        for (int rep = 0; rep < 4; rep++) {
            const int c = rep * 256 + tid;          // 0..1023
            const int row = c >> 3, ch = c & 7;
            cp16(sb + t * TILE_B + row * ROWB + ch * 16,
                 gp[t] + (size_t)row * D_ + ko + ch * 8);
        }
    }
    asm volatile("cp.async.commit_group;" ::: "memory");
}

// ---------------------------------------------------------------------------
// Single-pass fp16 GEMM: C = A @ W^T.
// MODE 0: fp32 row-major. MODE 1: fp16 head-scatter via gridDim.z.
// ---------------------------------------------------------------------------
template <int MODE>
__global__ void __launch_bounds__(256, 2) gemm_mma(const __half* __restrict__ A,
                                                   const __half* __restrict__ Wh,
                                                   void* __restrict__ outv) {
    extern __shared__ char sm[];
    const int tid = threadIdx.x;
    const int lane = tid & 31, wid = tid >> 5;
    const int mw = wid & 1, nw = wid >> 1;
    const int r0 = blockIdx.y * TM, n0 = blockIdx.x * TN;
    const int z = blockIdx.z;

    const __half* A_t = A + (size_t)r0 * D_;
    const __half* W_t = Wh + (size_t)z * D_ * D_ + (size_t)n0 * D_;

    float acc[4][4][4];
#pragma unroll
    for (int i = 0; i < 4; i++)
#pragma unroll
        for (int j = 0; j < 4; j++)
#pragma unroll
            for (int k = 0; k < 4; k++) acc[i][j][k] = 0.f;

    cp_stage(sm + 0 * STAGE_B, A_t, W_t, 0 * KS, tid);
    cp_stage(sm + 1 * STAGE_B, A_t, W_t, 1 * KS, tid);

    const uint32_t lrow = (lane & 15);
    const uint32_t lh = (lane >> 4) * 16;

    for (int kc = 0; kc < NK2; kc++) {
        const int s = kc % NSTG;
        if (kc + 1 < NK2) { CP_WAIT(1); } else { CP_WAIT(0); }
        __syncthreads();
        // Prefetch stage kc+2 (its buffer's readers finished before the sync above).
        if (kc + 2 < NK2)
            cp_stage(sm + ((kc + 2) % NSTG) * STAGE_B, A_t, W_t, (kc + 2) * KS, tid);

        const uint32_t sb = smem_u32(sm + s * STAGE_B);
#pragma unroll
        for (int kt = 0; kt < 4; kt++) {
            uint32_t bw[2][4];
#pragma unroll
            for (int np = 0; np < 2; np++)
                LDSM4(bw[np], sb + TILE_B + (nw * 32 + np * 16 + lrow) * ROWB + kt * 32 + lh);
#pragma unroll
            for (int mt = 0; mt < 4; mt++) {
                uint32_t ar[4];
                LDSM4(ar, sb + (mw * 64 + mt * 16 + lrow) * ROWB + kt * 32 + lh);
#pragma unroll
                for (int nt = 0; nt < 4; nt++)
                    MMAH(acc[mt][nt], ar, bw[nt >> 1][nt & 1], bw[nt >> 1][(nt & 1) + 2]);
            }
        }
    }

#pragma unroll
    for (int mt = 0; mt < 4; mt++) {
#pragma unroll
        for (int nt = 0; nt < 4; nt++) {
            const int row = r0 + mw * 64 + mt * 16 + (lane >> 2);
            const int col = n0 + nw * 32 + nt * 8 + 2 * (lane & 3);
            if (MODE == 1) {
                __half* out = (__half*)outv + (size_t)z * HSZ;
                const int h = col >> 6, dd = col & 63;
                const int bb0 = row >> 11, l0 = row & (L_ - 1);
                const int r8 = row + 8;
                const int bb1 = r8 >> 11, l1 = r8 & (L_ - 1);
                *(__half2*)(out + (((size_t)bb0 * H_ + h) * L_ + l0) * HD_ + dd) =
                    __floats2half2_rn(acc[mt][nt][0], acc[mt][nt][1]);
                *(__half2*)(out + (((size_t)bb1 * H_ + h) * L_ + l1) * HD_ + dd) =
                    __floats2half2_rn(acc[mt][nt][2], acc[mt][nt][3]);
            } else {
                float* out = (float*)outv;
                *(float2*)(out + (size_t)row * D_ + col) =
                    make_float2(acc[mt][nt][0], acc[mt][nt][1]);
                *(float2*)(out + (size_t)(row + 8) * D_ + col) =
                    make_float2(acc[mt][nt][2], acc[mt][nt][3]);
            }
        }
    }
}

// ---------------------------------------------------------------------------
// Fused prep: X->fp16, W0..W3->fp16, RoPE table. One launch.
// ---------------------------------------------------------------------------
constexpr int XN4 = M_ * D_ / 4;
constexpr int WN4 = D_ * D_ / 4;
constexpr int PREP_N = XN4 + 4 * WN4 + L_ * 32;

__global__ void prep_kernel(const float4* __restrict__ X,
                            const float4* __restrict__ W0, const float4* __restrict__ W1,
                            const float4* __restrict__ W2, const float4* __restrict__ W3) {
    const int i = blockIdx.x * blockDim.x + threadIdx.x;
    if (i < XN4) {
        const float4 v = X[i];
        __half2* o = (__half2*)g_Xh;
        o[2 * i]     = __floats2half2_rn(v.x, v.y);
        o[2 * i + 1] = __floats2half2_rn(v.z, v.w);
    } else if (i < XN4 + 4 * WN4) {
        const int widx = i - XN4;
        const int wi = widx >> 18, off = widx & (WN4 - 1);
        const float4* Wp = (wi == 0) ? W0 : (wi == 1) ? W1 : (wi == 2) ? W2 : W3;
        const float4 v = Wp[off];
        __half2* o = (__half2*)(g_Wh + (size_t)wi * D_ * D_);
        o[2 * off]     = __floats2half2_rn(v.x, v.y);
        o[2 * off + 1] = __floats2half2_rn(v.z, v.w);
    } else {
        const int r = i - XN4 - 4 * WN4;
        if (r < L_ * 32) {
            const int j = r & 31, l = r >> 5;
            const float invf = expf(-(float)j * 0.28782313662425575f);
            float s, c;
            sincosf((float)l * invf, &s, &c);
            g_cos[r] = c;
            g_sin[r] = s;
        }
    }
}

// ---------------------------------------------------------------------------
// Sliding-window attention, key-split halves + flash merge (R7 version).
// ---------------------------------------------------------------------------
__global__ void __launch_bounds__(256, 2) attn_mma() {
    extern __shared__ char sm[];
    const uint32_t sb = smem_u32(sm);
    const int tid = threadIdx.x;
    const int lane = tid & 31, w = tid >> 5;
    const int half = w >> 2, wq = w & 3;
    const int kbase = half * 96;
    const int bh = blockIdx.y;
    const int q0 = blockIdx.x * AQ;
    const int ks0 = q0 - (WINDOW_ - 1);
    const int jmin = (q0 < WINDOW_ - 1) ? (WINDOW_ - 1 - q0) : 0;

    const __half* Qg = g_QKVh + (size_t)bh * L_ * HD_ + (size_t)q0 * HD_;
    for (int idx = tid; idx < AQ * 8; idx += 256) {
        const int row = idx >> 3, d0 = (idx & 7) * 4;
        const __half* qp = Qg + (size_t)row * HD_ + d0;
        const uint2 ua = *(const uint2*)qp;
        const uint2 ub = *(const uint2*)(qp + 32);
        const __half2* ha = (const __half2*)&ua;
        const __half2* hb = (const __half2*)&ub;
        const float a[4] = {__low2float(ha[0]), __high2float(ha[0]),
                            __low2float(ha[1]), __high2float(ha[1])};
        const float b[4] = {__low2float(hb[0]), __high2float(hb[0]),
                            __low2float(hb[1]), __high2float(hb[1])};
        const float4 cc = *(const float4*)(g_cos + (q0 + row) * 32 + d0);
        const float4 ss = *(const float4*)(g_sin + (q0 + row) * 32 + d0);
        const float c[4] = {cc.x, cc.y, cc.z, cc.w};
        const float s[4] = {ss.x, ss.y, ss.z, ss.w};
        char* p = sm + OFF_Q + row * ASTR + d0 * 2;
#pragma unroll
        for (int e = 0; e < 4; e += 2) {
            *(__half2*)(p + e * 2) = __floats2half2_rn(a[e] * c[e] - b[e] * s[e],
                                                       a[e + 1] * c[e + 1] - b[e + 1] * s[e + 1]);
            *(__half2*)(p + 64 + e * 2) = __floats2half2_rn(b[e] * c[e] + a[e] * s[e],
                                                            b[e + 1] * c[e + 1] + a[e + 1] * s[e + 1]);
        }
    }
    const __half* Kg = g_QKVh + HSZ + (size_t)bh * L_ * HD_;
    for (int idx = tid; idx < ANK * 8; idx += 256) {
        const int row = idx >> 3, d0 = (idx & 7) * 4;
        const int kg = ks0 + row;
        char* p = sm + OFF_K + row * ASTR + d0 * 2;
        if (kg < 0) {
            *(uint2*)p = make_uint2(0, 0);
            *(uint2*)(p + 64) = make_uint2(0, 0);
            continue;
        }
        const __half* kp = Kg + (size_t)kg * HD_ + d0;
        const uint2 ua = *(const uint2*)kp;
        const uint2 ub = *(const uint2*)(kp + 32);
        const __half2* ha = (const __half2*)&ua;
        const __half2* hb = (const __half2*)&ub;
        const float a[4] = {__low2float(ha[0]), __high2float(ha[0]),
                            __low2float(ha[1]), __high2float(ha[1])};
        const float b[4] = {__low2float(hb[0]), __high2float(hb[0]),
                            __low2float(hb[1]), __high2float(hb[1])};
        const float4 cc = *(const float4*)(g_cos + kg * 32 + d0);
        const float4 ss = *(const float4*)(g_sin + kg * 32 + d0);
        const float c[4] = {cc.x, cc.y, cc.z, cc.w};
        const float s[4] = {ss.x, ss.y, ss.z, ss.w};
#pragma unroll
        for (int e = 0; e < 4; e += 2) {
            *(__half2*)(p + e * 2) = __floats2half2_rn(a[e] * c[e] - b[e] * s[e],
                                                       a[e + 1] * c[e + 1] - b[e + 1] * s[e + 1]);
            *(__half2*)(p + 64 + e * 2) = __floats2half2_rn(b[e] * c[e] + a[e] * s[e],
                                                            b[e + 1] * c[e + 1] + a[e + 1] * s[e + 1]);
        }
    }
    const __half* Vg = g_QKVh + 2 * HSZ + (size_t)bh * L_ * HD_;
    for (int idx = tid; idx < ANK * 8; idx += 256) {
        const int row = idx >> 3, c8 = idx & 7;
        const int kg = ks0 + row;
        uint4 v = make_uint4(0, 0, 0, 0);
        if (kg >= 0) v = *(const uint4*)(Vg + (size_t)kg * HD_ + c8 * 8);
        *(uint4*)(sm + OFF_V + row * ASTR + c8 * 16) = v;
    }
    __syncthreads();

    float sac[12][4];
#pragma unroll
    for (int f = 0; f < 12; f++)
#pragma unroll
        for (int k = 0; k < 4; k++) sac[f][k] = 0.f;

    const uint32_t lrow = (lane & 15);
    const uint32_t lh = (lane >> 4) * 16;
#pragma unroll
    for (int kt = 0; kt < 4; kt++) {
        uint32_t aq[4];
        LDSM4(aq, sb + OFF_Q + (16 * wq + lrow) * ASTR + kt * 32 + lh);
#pragma unroll
        for (int nb = 0; nb < 6; nb++) {
            uint32_t bk[4];
            LDSM4(bk, sb + OFF_K + (kbase + nb * 16 + lrow) * ASTR + kt * 32 + lh);
            MMAH(sac[2 * nb],     aq, bk[0], bk[2]);
            MMAH(sac[2 * nb + 1], aq, bk[1], bk[3]);
        }
    }

    const int i1 = 16 * wq + (lane >> 2);
    const int i2 = i1 + 8;
    const int cq = (lane & 3) * 2;
    constexpr float SCALE = 0.125f;
    float m1 = -1e30f, m2 = -1e30f;
#pragma unroll
    for (int f = 0; f < 12; f++) {
        const int j0 = kbase + 8 * f + cq, j1 = j0 + 1;
        const bool k00 = ((unsigned)(j0 - i1) < (unsigned)WINDOW_) && j0 >= jmin;
        const bool k01 = ((unsigned)(j1 - i1) < (unsigned)WINDOW_) && j1 >= jmin;
        const bool k10 = ((unsigned)(j0 - i2) < (unsigned)WINDOW_) && j0 >= jmin;
        const bool k11 = ((unsigned)(j1 - i2) < (unsigned)WINDOW_) && j1 >= jmin;
        sac[f][0] = k00 ? sac[f][0] * SCALE : -1e30f;
        sac[f][1] = k01 ? sac[f][1] * SCALE : -1e30f;
        sac[f][2] = k10 ? sac[f][2] * SCALE : -1e30f;
        sac[f][3] = k11 ? sac[f][3] * SCALE : -1e30f;
        m1 = fmaxf(m1, fmaxf(sac[f][0], sac[f][1]));
        m2 = fmaxf(m2, fmaxf(sac[f][2], sac[f][3]));
    }
    m1 = fmaxf(m1, __shfl_xor_sync(0xffffffffu, m1, 1));
    m1 = fmaxf(m1, __shfl_xor_sync(0xffffffffu, m1, 2));
    m2 = fmaxf(m2, __shfl_xor_sync(0xffffffffu, m2, 1));
    m2 = fmaxf(m2, __shfl_xor_sync(0xffffffffu, m2, 2));

    float l1 = 0.f, l2 = 0.f;
#pragma unroll
    for (int f = 0; f < 12; f++) {
        sac[f][0] = __expf(sac[f][0] - m1);
        sac[f][1] = __expf(sac[f][1] - m1);
        sac[f][2] = __expf(sac[f][2] - m2);
        sac[f][3] = __expf(sac[f][3] - m2);
        l1 += sac[f][0] + sac[f][1];
        l2 += sac[f][2] + sac[f][3];
    }
    l1 += __shfl_xor_sync(0xffffffffu, l1, 1);
    l1 += __shfl_xor_sync(0xffffffffu, l1, 2);
    l2 += __shfl_xor_sync(0xffffffffu, l2, 1);
    l2 += __shfl_xor_sync(0xffffffffu, l2, 2);

    float oac[8][4];
#pragma unroll
    for (int f = 0; f < 8; f++)
#pragma unroll
        for (int k = 0; k < 4; k++) oac[f][k] = 0.f;

#pragma unroll
    for (int kb = 0; kb < 6; kb++) {
        uint32_t pa[4];
        pa[0] = pack_h2(sac[2 * kb][0],     sac[2 * kb][1]);
        pa[1] = pack_h2(sac[2 * kb][2],     sac[2 * kb][3]);
        pa[2] = pack_h2(sac[2 * kb + 1][0], sac[2 * kb + 1][1]);
        pa[3] = pack_h2(sac[2 * kb + 1][2], sac[2 * kb + 1][3]);
#pragma unroll
        for (int db = 0; db < 4; db++) {
            uint32_t bv[4];
            LDSM4T(bv, sb + OFF_V + (kbase + kb * 16 + lrow) * ASTR + db * 32 + lh);
            MMAH(oac[2 * db],     pa, bv[0], bv[1]);
            MMAH(oac[2 * db + 1], pa, bv[2], bv[3]);
        }
    }

    float* O1 = (float*)(sm + OFF_O1);
    float* sm_m = (float*)(sm + OFF_M1);
    float* sm_l = (float*)(sm + OFF_L1);

    if (half == 0) {
#pragma unroll
        for (int f = 0; f < 8; f++) {
            const int d0 = 8 * f + cq;
            O1[i1 * 66 + d0]     = oac[f][0];
            O1[i1 * 66 + d0 + 1] = oac[f][1];
            O1[i2 * 66 + d0]     = oac[f][2];
            O1[i2 * 66 + d0 + 1] = oac[f][3];
        }
        if ((lane & 3) == 0) {
            sm_m[i1] = m1; sm_l[i1] = l1;
            sm_m[i2] = m2; sm_l[i2] = l2;
        }
    }
    __syncthreads();

    if (half == 1) {
        const float m1s = sm_m[i1], l1s = sm_l[i1];
        const float m2s = sm_m[i2], l2s = sm_l[i2];
        const float M1 = fmaxf(m1s, m1), M2 = fmaxf(m2s, m2);
        const float a1 = __expf(m1s - M1), b1 = __expf(m1 - M1);
        const float a2 = __expf(m2s - M2), b2 = __expf(m2 - M2);
        const float inv1 = 1.f / (a1 * l1s + b1 * l1);
        const float inv2 = 1.f / (a2 * l2s + b2 * l2);

        const int bb = bh >> 4, h = bh & (H_ - 1);
        const size_t off1 = ((size_t)bb * L_ + q0 + i1) * D_ + h * HD_;
        const size_t off2 = ((size_t)bb * L_ + q0 + i2) * D_ + h * HD_;
#pragma unroll
        for (int f = 0; f < 8; f++) {
            const int d0 = 8 * f + cq;
            const float v10 = (a1 * O1[i1 * 66 + d0]     + b1 * oac[f][0]) * inv1;
            const float v11 = (a1 * O1[i1 * 66 + d0 + 1] + b1 * oac[f][1]) * inv1;
            const float v20 = (a2 * O1[i2 * 66 + d0]     + b2 * oac[f][2]) * inv2;
            const float v21 = (a2 * O1[i2 * 66 + d0 + 1] + b2 * oac[f][3]) * inv2;
            *(__half2*)(g_Sh + off1 + d0) = __floats2half2_rn(v10, v11);
            *(__half2*)(g_Sh + off2 + d0) = __floats2half2_rn(v20, v21);
        }
    }
}

// ---------------------------------------------------------------------------
extern "C" void kernel_launch(void* const* d_in, const int* in_sizes, int n_in,
                              void* d_out, int out_size) {
    const float* X = (const float*)d_in[0];
    float* out = (float*)d_out;

    __half *QKVh, *Sh, *Xh, *Wh;
    cudaGetSymbolAddress((void**)&QKVh, g_QKVh);
    cudaGetSymbolAddress((void**)&Sh, g_Sh);
    cudaGetSymbolAddress((void**)&Xh, g_Xh);
    cudaGetSymbolAddress((void**)&Wh, g_Wh);

    cudaFuncSetAttribute(gemm_mma<0>, cudaFuncAttributeMaxDynamicSharedMemorySize, GSMEM);
    cudaFuncSetAttribute(gemm_mma<1>, cudaFuncAttributeMaxDynamicSharedMemorySize, GSMEM);
    cudaFuncSetAttribute(attn_mma, cudaFuncAttributeMaxDynamicSharedMemorySize, ASMEM);

    prep_kernel<<<(PREP_N + 255) / 256, 256>>>((const float4*)X,
                                               (const float4*)d_in[1], (const float4*)d_in[2],
                                               (const float4*)d_in[3], (const float4*)d_in[4]);

    gemm_mma<1><<<dim3(D_ / TN, M_ / TM, 3), 256, GSMEM>>>(Xh, Wh, QKVh);

    attn_mma<<<dim3(L_ / AQ, B_ * H_), 256, ASMEM>>>();

    gemm_mma<0><<<dim3(D_ / TN, M_ / TM, 1), 256, GSMEM>>>(Sh, Wh + 3 * (size_t)D_ * D_, out);
}

// round 9
// speedup vs baseline: 9.6577x; 1.0177x over previous
#include <cuda_runtime.h>
#include <cuda_fp16.h>
#include <math.h>
#include <stdint.h>

// Problem constants
constexpr int B_ = 4, L_ = 2048, D_ = 1024, H_ = 16, HD_ = 64;
constexpr int M_ = B_ * L_;
constexpr int WINDOW_ = 128;
constexpr size_t HSZ = (size_t)B_ * H_ * L_ * HD_;

// GEMM tiling: CTA 128x128, K-step 64, 3-stage, 1 sync/iter, reg double-buffer.
constexpr int TM = 128, TN = 128, KS = 64;
constexpr int NK2 = D_ / KS;                // 16 iterations
constexpr int ROWB = 144;
constexpr int TILE_B = 128 * ROWB;          // 18432
constexpr int STAGE_B = 2 * TILE_B;         // 36864
constexpr int NSTG = 3;
constexpr int GSMEM = NSTG * STAGE_B;       // 110592

// Attention tiling
constexpr int AQ = 64;
constexpr int ANK = 192;
constexpr int ASTR = 144;
constexpr int OFF_Q = 0;
constexpr int OFF_K = OFF_Q + AQ * ASTR;
constexpr int OFF_V = OFF_K + ANK * ASTR;
constexpr int OFF_O1 = OFF_V + ANK * ASTR;
constexpr int OFF_M1 = OFF_O1 + 64 * 66 * 4;
constexpr int OFF_L1 = OFF_M1 + 64 * 4;
constexpr int ASMEM = OFF_L1 + 64 * 4;      // 81920

// Scratch (device globals)
__device__ __half g_QKVh[3 * HSZ];
__device__ __half g_Sh[(size_t)M_ * D_];
__device__ __half g_Xh[(size_t)M_ * D_];
__device__ __half g_Wh[4ull * D_ * D_];
__device__ float g_cos[L_ * 32];
__device__ float g_sin[L_ * 32];

__device__ __forceinline__ uint32_t smem_u32(const void* p) {
    uint32_t a;
    asm("{ .reg .u64 t; cvta.to.shared.u64 t, %1; cvt.u32.u64 %0, t; }" : "=r"(a) : "l"(p));
    return a;
}

#define LDSM4(r, addr) \
    asm volatile("ldmatrix.sync.aligned.m8n8.x4.shared.b16 {%0,%1,%2,%3}, [%4];" \
                 : "=r"((r)[0]), "=r"((r)[1]), "=r"((r)[2]), "=r"((r)[3]) : "r"(addr))

#define LDSM4T(r, addr) \
    asm volatile("ldmatrix.sync.aligned.m8n8.x4.trans.shared.b16 {%0,%1,%2,%3}, [%4];" \
                 : "=r"((r)[0]), "=r"((r)[1]), "=r"((r)[2]), "=r"((r)[3]) : "r"(addr))

#define MMAH(d, a, b0, b1) \
    asm volatile("mma.sync.aligned.m16n8k16.row.col.f32.f16.f16.f32 " \
                 "{%0,%1,%2,%3}, {%4,%5,%6,%7}, {%8,%9}, {%0,%1,%2,%3};" \
                 : "+f"((d)[0]), "+f"((d)[1]), "+f"((d)[2]), "+f"((d)[3]) \
                 : "r"((a)[0]), "r"((a)[1]), "r"((a)[2]), "r"((a)[3]), "r"(b0), "r"(b1))

#define CP_WAIT(n) asm volatile("cp.async.wait_group %0;" :: "n"(n) : "memory")

__device__ __forceinline__ void cp16(uint32_t sa, const void* g) {
    asm volatile("cp.async.cg.shared.global [%0], [%1], 16;" :: "r"(sa), "l"(g));
}

__device__ __forceinline__ uint32_t pack_h2(float lo, float hi) {
    __half2 h = __floats2half2_rn(lo, hi);
    return *(uint32_t*)&h;
}

__device__ __forceinline__ void cp_stage(char* st, const __half* a, const __half* wt,
                                         int ko, int tid) {
    const __half* gp[2] = {a, wt};
    const uint32_t sb = smem_u32(st);
#pragma unroll
    for (int t = 0; t < 2; t++) {
#pragma unroll
        for (int rep = 0; rep < 4; rep++) {
            const int c = rep * 256 + tid;
            const int row = c >> 3, ch = c & 7;
            cp16(sb + t * TILE_B + row * ROWB + ch * 16,
                 gp[t] + (size_t)row * D_ + ko + ch * 8);
        }
    }
    asm volatile("cp.async.commit_group;" ::: "memory");
}

// ---------------------------------------------------------------------------
// Single-pass fp16 GEMM with register-level A/B fragment double buffering.
// ---------------------------------------------------------------------------
template <int MODE>
__global__ void __launch_bounds__(256, 2) gemm_mma(const __half* __restrict__ A,
                                                   const __half* __restrict__ Wh,
                                                   void* __restrict__ outv) {
    extern __shared__ char sm[];
    const int tid = threadIdx.x;
    const int lane = tid & 31, wid = tid >> 5;
    const int mw = wid & 1, nw = wid >> 1;
    const int r0 = blockIdx.y * TM, n0 = blockIdx.x * TN;
    const int z = blockIdx.z;

    const __half* A_t = A + (size_t)r0 * D_;
    const __half* W_t = Wh + (size_t)z * D_ * D_ + (size_t)n0 * D_;

    float acc[4][4][4];
#pragma unroll
    for (int i = 0; i < 4; i++)
#pragma unroll
        for (int j = 0; j < 4; j++)
#pragma unroll
            for (int k = 0; k < 4; k++) acc[i][j][k] = 0.f;

    cp_stage(sm + 0 * STAGE_B, A_t, W_t, 0 * KS, tid);
    cp_stage(sm + 1 * STAGE_B, A_t, W_t, 1 * KS, tid);

    const uint32_t lrow = (lane & 15);
    const uint32_t lh = (lane >> 4) * 16;
    const uint32_t arow = (mw * 64 + lrow) * ROWB + lh;   // + mt*16*ROWB + kt*32
    const uint32_t brow = (nw * 32 + lrow) * ROWB + lh;   // + np*16*ROWB + kt*32

    for (int kc = 0; kc < NK2; kc++) {
        const int s = kc % NSTG;
        if (kc + 1 < NK2) { CP_WAIT(1); } else { CP_WAIT(0); }
        __syncthreads();

        const uint32_t sb = smem_u32(sm + s * STAGE_B);
        uint32_t Bb[2][2][4];
        uint32_t Ab[2][4];
        // Prime kt=0 fragments before issuing the bulk cp.async batch.
        LDSM4(Bb[0][0], sb + TILE_B + brow);
        LDSM4(Bb[0][1], sb + TILE_B + brow + 16 * ROWB);
        LDSM4(Ab[0], sb + arow);

        if (kc + 2 < NK2)
            cp_stage(sm + ((kc + 2) % NSTG) * STAGE_B, A_t, W_t, (kc + 2) * KS, tid);

#pragma unroll
        for (int kt = 0; kt < 4; kt++) {
            const int bc = kt & 1;
            if (kt < 3) {
                LDSM4(Bb[bc ^ 1][0], sb + TILE_B + brow + (kt + 1) * 32);
                LDSM4(Bb[bc ^ 1][1], sb + TILE_B + brow + 16 * ROWB + (kt + 1) * 32);
            }
#pragma unroll
            for (int mt = 0; mt < 4; mt++) {
                const int ac = mt & 1;
                if (mt < 3) {
                    LDSM4(Ab[ac ^ 1], sb + arow + (mt + 1) * 16 * ROWB + kt * 32);
                } else if (kt < 3) {
                    LDSM4(Ab[ac ^ 1], sb + arow + (kt + 1) * 32);
                }
#pragma unroll
                for (int nt = 0; nt < 4; nt++)
                    MMAH(acc[mt][nt], Ab[ac],
                         Bb[bc][nt >> 1][nt & 1], Bb[bc][nt >> 1][(nt & 1) + 2]);
            }
        }
    }

#pragma unroll
    for (int mt = 0; mt < 4; mt++) {
#pragma unroll
        for (int nt = 0; nt < 4; nt++) {
            const int row = r0 + mw * 64 + mt * 16 + (lane >> 2);
            const int col = n0 + nw * 32 + nt * 8 + 2 * (lane & 3);
            if (MODE == 1) {
                __half* out = (__half*)outv + (size_t)z * HSZ;
                const int h = col >> 6, dd = col & 63;
                const int bb0 = row >> 11, l0 = row & (L_ - 1);
                const int r8 = row + 8;
                const int bb1 = r8 >> 11, l1 = r8 & (L_ - 1);
                *(__half2*)(out + (((size_t)bb0 * H_ + h) * L_ + l0) * HD_ + dd) =
                    __floats2half2_rn(acc[mt][nt][0], acc[mt][nt][1]);
                *(__half2*)(out + (((size_t)bb1 * H_ + h) * L_ + l1) * HD_ + dd) =
                    __floats2half2_rn(acc[mt][nt][2], acc[mt][nt][3]);
            } else {
                float* out = (float*)outv;
                *(float2*)(out + (size_t)row * D_ + col) =
                    make_float2(acc[mt][nt][0], acc[mt][nt][1]);
                *(float2*)(out + (size_t)(row + 8) * D_ + col) =
                    make_float2(acc[mt][nt][2], acc[mt][nt][3]);
            }
        }
    }
}

// ---------------------------------------------------------------------------
// Fused prep: X->fp16, W0..W3->fp16, RoPE table.
// ---------------------------------------------------------------------------
constexpr int XN4 = M_ * D_ / 4;
constexpr int WN4 = D_ * D_ / 4;
constexpr int PREP_N = XN4 + 4 * WN4 + L_ * 32;

__global__ void prep_kernel(const float4* __restrict__ X,
                            const float4* __restrict__ W0, const float4* __restrict__ W1,
                            const float4* __restrict__ W2, const float4* __restrict__ W3) {
    const int i = blockIdx.x * blockDim.x + threadIdx.x;
    if (i < XN4) {
        const float4 v = X[i];
        __half2* o = (__half2*)g_Xh;
        o[2 * i]     = __floats2half2_rn(v.x, v.y);
        o[2 * i + 1] = __floats2half2_rn(v.z, v.w);
    } else if (i < XN4 + 4 * WN4) {
        const int widx = i - XN4;
        const int wi = widx >> 18, off = widx & (WN4 - 1);
        const float4* Wp = (wi == 0) ? W0 : (wi == 1) ? W1 : (wi == 2) ? W2 : W3;
        const float4 v = Wp[off];
        __half2* o = (__half2*)(g_Wh + (size_t)wi * D_ * D_);
        o[2 * off]     = __floats2half2_rn(v.x, v.y);
        o[2 * off + 1] = __floats2half2_rn(v.z, v.w);
    } else {
        const int r = i - XN4 - 4 * WN4;
        if (r < L_ * 32) {
            const int j = r & 31, l = r >> 5;
            const float invf = expf(-(float)j * 0.28782313662425575f);
            float s, c;
            sincosf((float)l * invf, &s, &c);
            g_cos[r] = c;
            g_sin[r] = s;
        }
    }
}

// ---------------------------------------------------------------------------
// Sliding-window attention, key-split halves + flash merge.
// ---------------------------------------------------------------------------
__global__ void __launch_bounds__(256, 2) attn_mma() {
    extern __shared__ char sm[];
    const uint32_t sb = smem_u32(sm);
    const int tid = threadIdx.x;
    const int lane = tid & 31, w = tid >> 5;
    const int half = w >> 2, wq = w & 3;
    const int kbase = half * 96;
    const int bh = blockIdx.y;
    const int q0 = blockIdx.x * AQ;
    const int ks0 = q0 - (WINDOW_ - 1);
    const int jmin = (q0 < WINDOW_ - 1) ? (WINDOW_ - 1 - q0) : 0;

    const __half* Qg = g_QKVh + (size_t)bh * L_ * HD_ + (size_t)q0 * HD_;
    for (int idx = tid; idx < AQ * 8; idx += 256) {
        const int row = idx >> 3, d0 = (idx & 7) * 4;
        const __half* qp = Qg + (size_t)row * HD_ + d0;
        const uint2 ua = *(const uint2*)qp;
        const uint2 ub = *(const uint2*)(qp + 32);
        const __half2* ha = (const __half2*)&ua;
        const __half2* hb = (const __half2*)&ub;
        const float a[4] = {__low2float(ha[0]), __high2float(ha[0]),
                            __low2float(ha[1]), __high2float(ha[1])};
        const float b[4] = {__low2float(hb[0]), __high2float(hb[0]),
                            __low2float(hb[1]), __high2float(hb[1])};
        const float4 cc = *(const float4*)(g_cos + (q0 + row) * 32 + d0);
        const float4 ss = *(const float4*)(g_sin + (q0 + row) * 32 + d0);
        const float c[4] = {cc.x, cc.y, cc.z, cc.w};
        const float s[4] = {ss.x, ss.y, ss.z, ss.w};
        char* p = sm + OFF_Q + row * ASTR + d0 * 2;
#pragma unroll
        for (int e = 0; e < 4; e += 2) {
            *(__half2*)(p + e * 2) = __floats2half2_rn(a[e] * c[e] - b[e] * s[e],
                                                       a[e + 1] * c[e + 1] - b[e + 1] * s[e + 1]);
            *(__half2*)(p + 64 + e * 2) = __floats2half2_rn(b[e] * c[e] + a[e] * s[e],
                                                            b[e + 1] * c[e + 1] + a[e + 1] * s[e + 1]);
        }
    }
    const __half* Kg = g_QKVh + HSZ + (size_t)bh * L_ * HD_;
    for (int idx = tid; idx < ANK * 8; idx += 256) {
        const int row = idx >> 3, d0 = (idx & 7) * 4;
        const int kg = ks0 + row;
        char* p = sm + OFF_K + row * ASTR + d0 * 2;
        if (kg < 0) {
            *(uint2*)p = make_uint2(0, 0);
            *(uint2*)(p + 64) = make_uint2(0, 0);
            continue;
        }
        const __half* kp = Kg + (size_t)kg * HD_ + d0;
        const uint2 ua = *(const uint2*)kp;
        const uint2 ub = *(const uint2*)(kp + 32);
        const __half2* ha = (const __half2*)&ua;
        const __half2* hb = (const __half2*)&ub;
        const float a[4] = {__low2float(ha[0]), __high2float(ha[0]),
                            __low2float(ha[1]), __high2float(ha[1])};
        const float b[4] = {__low2float(hb[0]), __high2float(hb[0]),
                            __low2float(hb[1]), __high2float(hb[1])};
        const float4 cc = *(const float4*)(g_cos + kg * 32 + d0);
        const float4 ss = *(const float4*)(g_sin + kg * 32 + d0);
        const float c[4] = {cc.x, cc.y, cc.z, cc.w};
        const float s[4] = {ss.x, ss.y, ss.z, ss.w};
#pragma unroll
        for (int e = 0; e < 4; e += 2) {
            *(__half2*)(p + e * 2) = __floats2half2_rn(a[e] * c[e] - b[e] * s[e],
                                                       a[e + 1] * c[e + 1] - b[e + 1] * s[e + 1]);
            *(__half2*)(p + 64 + e * 2) = __floats2half2_rn(b[e] * c[e] + a[e] * s[e],
                                                            b[e + 1] * c[e + 1] + a[e + 1] * s[e + 1]);
        }
    }
    const __half* Vg = g_QKVh + 2 * HSZ + (size_t)bh * L_ * HD_;
    for (int idx = tid; idx < ANK * 8; idx += 256) {
        const int row = idx >> 3, c8 = idx & 7;
        const int kg = ks0 + row;
        uint4 v = make_uint4(0, 0, 0, 0);
        if (kg >= 0) v = *(const uint4*)(Vg + (size_t)kg * HD_ + c8 * 8);
        *(uint4*)(sm + OFF_V + row * ASTR + c8 * 16) = v;
    }
    __syncthreads();

    float sac[12][4];
#pragma unroll
    for (int f = 0; f < 12; f++)
#pragma unroll
        for (int k = 0; k < 4; k++) sac[f][k] = 0.f;

    const uint32_t lrow = (lane & 15);
    const uint32_t lh = (lane >> 4) * 16;
#pragma unroll
    for (int kt = 0; kt < 4; kt++) {
        uint32_t aq[4];
        LDSM4(aq, sb + OFF_Q + (16 * wq + lrow) * ASTR + kt * 32 + lh);
#pragma unroll
        for (int nb = 0; nb < 6; nb++) {
            uint32_t bk[4];
            LDSM4(bk, sb + OFF_K + (kbase + nb * 16 + lrow) * ASTR + kt * 32 + lh);
            MMAH(sac[2 * nb],     aq, bk[0], bk[2]);
            MMAH(sac[2 * nb + 1], aq, bk[1], bk[3]);
        }
    }

    const int i1 = 16 * wq + (lane >> 2);
    const int i2 = i1 + 8;
    const int cq = (lane & 3) * 2;
    constexpr float SCALE = 0.125f;
    float m1 = -1e30f, m2 = -1e30f;
#pragma unroll
    for (int f = 0; f < 12; f++) {
        const int j0 = kbase + 8 * f + cq, j1 = j0 + 1;
        const bool k00 = ((unsigned)(j0 - i1) < (unsigned)WINDOW_) && j0 >= jmin;
        const bool k01 = ((unsigned)(j1 - i1) < (unsigned)WINDOW_) && j1 >= jmin;
        const bool k10 = ((unsigned)(j0 - i2) < (unsigned)WINDOW_) && j0 >= jmin;
        const bool k11 = ((unsigned)(j1 - i2) < (unsigned)WINDOW_) && j1 >= jmin;
        sac[f][0] = k00 ? sac[f][0] * SCALE : -1e30f;
        sac[f][1] = k01 ? sac[f][1] * SCALE : -1e30f;
        sac[f][2] = k10 ? sac[f][2] * SCALE : -1e30f;
        sac[f][3] = k11 ? sac[f][3] * SCALE : -1e30f;
        m1 = fmaxf(m1, fmaxf(sac[f][0], sac[f][1]));
        m2 = fmaxf(m2, fmaxf(sac[f][2], sac[f][3]));
    }
    m1 = fmaxf(m1, __shfl_xor_sync(0xffffffffu, m1, 1));
    m1 = fmaxf(m1, __shfl_xor_sync(0xffffffffu, m1, 2));
    m2 = fmaxf(m2, __shfl_xor_sync(0xffffffffu, m2, 1));
    m2 = fmaxf(m2, __shfl_xor_sync(0xffffffffu, m2, 2));

    float l1 = 0.f, l2 = 0.f;
#pragma unroll
    for (int f = 0; f < 12; f++) {
        sac[f][0] = __expf(sac[f][0] - m1);
        sac[f][1] = __expf(sac[f][1] - m1);
        sac[f][2] = __expf(sac[f][2] - m2);
        sac[f][3] = __expf(sac[f][3] - m2);
        l1 += sac[f][0] + sac[f][1];
        l2 += sac[f][2] + sac[f][3];
    }
    l1 += __shfl_xor_sync(0xffffffffu, l1, 1);
    l1 += __shfl_xor_sync(0xffffffffu, l1, 2);
    l2 += __shfl_xor_sync(0xffffffffu, l2, 1);
    l2 += __shfl_xor_sync(0xffffffffu, l2, 2);

    float oac[8][4];
#pragma unroll
    for (int f = 0; f < 8; f++)
#pragma unroll
        for (int k = 0; k < 4; k++) oac[f][k] = 0.f;

#pragma unroll
    for (int kb = 0; kb < 6; kb++) {
        uint32_t pa[4];
        pa[0] = pack_h2(sac[2 * kb][0],     sac[2 * kb][1]);
        pa[1] = pack_h2(sac[2 * kb][2],     sac[2 * kb][3]);
        pa[2] = pack_h2(sac[2 * kb + 1][0], sac[2 * kb + 1][1]);
        pa[3] = pack_h2(sac[2 * kb + 1][2], sac[2 * kb + 1][3]);
#pragma unroll
        for (int db = 0; db < 4; db++) {
            uint32_t bv[4];
            LDSM4T(bv, sb + OFF_V + (kbase + kb * 16 + lrow) * ASTR + db * 32 + lh);
            MMAH(oac[2 * db],     pa, bv[0], bv[1]);
            MMAH(oac[2 * db + 1], pa, bv[2], bv[3]);
        }
    }

    float* O1 = (float*)(sm + OFF_O1);
    float* sm_m = (float*)(sm + OFF_M1);
    float* sm_l = (float*)(sm + OFF_L1);

    if (half == 0) {
#pragma unroll
        for (int f = 0; f < 8; f++) {
            const int d0 = 8 * f + cq;
            O1[i1 * 66 + d0]     = oac[f][0];
            O1[i1 * 66 + d0 + 1] = oac[f][1];
            O1[i2 * 66 + d0]     = oac[f][2];
            O1[i2 * 66 + d0 + 1] = oac[f][3];
        }
        if ((lane & 3) == 0) {
            sm_m[i1] = m1; sm_l[i1] = l1;
            sm_m[i2] = m2; sm_l[i2] = l2;
        }
    }
    __syncthreads();

    if (half == 1) {
        const float m1s = sm_m[i1], l1s = sm_l[i1];
        const float m2s = sm_m[i2], l2s = sm_l[i2];
        const float M1 = fmaxf(m1s, m1), M2 = fmaxf(m2s, m2);
        const float a1 = __expf(m1s - M1), b1 = __expf(m1 - M1);
        const float a2 = __expf(m2s - M2), b2 = __expf(m2 - M2);
        const float inv1 = 1.f / (a1 * l1s + b1 * l1);
        const float inv2 = 1.f / (a2 * l2s + b2 * l2);

        const int bb = bh >> 4, h = bh & (H_ - 1);
        const size_t off1 = ((size_t)bb * L_ + q0 + i1) * D_ + h * HD_;
        const size_t off2 = ((size_t)bb * L_ + q0 + i2) * D_ + h * HD_;
#pragma unroll
        for (int f = 0; f < 8; f++) {
            const int d0 = 8 * f + cq;
            const float v10 = (a1 * O1[i1 * 66 + d0]     + b1 * oac[f][0]) * inv1;
            const float v11 = (a1 * O1[i1 * 66 + d0 + 1] + b1 * oac[f][1]) * inv1;
            const float v20 = (a2 * O1[i2 * 66 + d0]     + b2 * oac[f][2]) * inv2;
            const float v21 = (a2 * O1[i2 * 66 + d0 + 1] + b2 * oac[f][3]) * inv2;
            *(__half2*)(g_Sh + off1 + d0) = __floats2half2_rn(v10, v11);
            *(__half2*)(g_Sh + off2 + d0) = __floats2half2_rn(v20, v21);
        }
    }
}

// ---------------------------------------------------------------------------
extern "C" void kernel_launch(void* const* d_in, const int* in_sizes, int n_in,
                              void* d_out, int out_size) {
    const float* X = (const float*)d_in[0];
    float* out = (float*)d_out;

    __half *QKVh, *Sh, *Xh, *Wh;
    cudaGetSymbolAddress((void**)&QKVh, g_QKVh);
    cudaGetSymbolAddress((void**)&Sh, g_Sh);
    cudaGetSymbolAddress((void**)&Xh, g_Xh);
    cudaGetSymbolAddress((void**)&Wh, g_Wh);

    cudaFuncSetAttribute(gemm_mma<0>, cudaFuncAttributeMaxDynamicSharedMemorySize, GSMEM);
    cudaFuncSetAttribute(gemm_mma<1>, cudaFuncAttributeMaxDynamicSharedMemorySize, GSMEM);
    cudaFuncSetAttribute(attn_mma, cudaFuncAttributeMaxDynamicSharedMemorySize, ASMEM);

    prep_kernel<<<(PREP_N + 255) / 256, 256>>>((const float4*)X,
                                               (const float4*)d_in[1], (const float4*)d_in[2],
                                               (const float4*)d_in[3], (const float4*)d_in[4]);

    gemm_mma<1><<<dim3(D_ / TN, M_ / TM, 3), 256, GSMEM>>>(Xh, Wh, QKVh);

    attn_mma<<<dim3(L_ / AQ, B_ * H_), 256, ASMEM>>>();

    gemm_mma<0><<<dim3(D_ / TN, M_ / TM, 1), 256, GSMEM>>>(Sh, Wh + 3 * (size_t)D_ * D_, out);
}